// round 3
// baseline (speedup 1.0000x reference)
#include <cuda_runtime.h>
#include <cstdint>

#define SEQ    2048
#define BATCH  4
#define NHEAD  16
#define DK     64
#define DMODEL 1024
#define MROWS  (BATCH*SEQ)

// Scratch (allocation-free rule: device globals).
__device__ float g_q[BATCH*NHEAD*SEQ*DK];
__device__ float g_k[BATCH*NHEAD*SEQ*DK];
__device__ float g_v[BATCH*NHEAD*SEQ*DK];
__device__ float g_ctx[(size_t)MROWS*DMODEL];
// tf32-pre-rounded copies of raw inputs
__device__ float g_xq[(size_t)MROWS*DMODEL];
__device__ float g_xk[(size_t)MROWS*DMODEL];
__device__ float g_xv[(size_t)MROWS*DMODEL];
__device__ float g_wq[DMODEL*DMODEL];
__device__ float g_wk[DMODEL*DMODEL];
__device__ float g_wv[DMODEL*DMODEL];
__device__ float g_wo[DMODEL*DMODEL];

// ---------------- helpers ----------------
__device__ __forceinline__ uint32_t f2tf(float x){
    uint32_t r; asm("cvt.rna.tf32.f32 %0, %1;" : "=r"(r) : "f"(x)); return r;
}
__device__ __forceinline__ float tff(float x){ return __uint_as_float(f2tf(x)); }
__device__ __forceinline__ uint32_t saddr(const void* p){
    return (uint32_t)__cvta_generic_to_shared(p);
}
__device__ __forceinline__ void cp16(uint32_t s, const void* g){
    asm volatile("cp.async.cg.shared.global [%0], [%1], 16;\n" :: "r"(s), "l"(g));
}
__device__ __forceinline__ void cpcommit(){ asm volatile("cp.async.commit_group;\n"); }
template<int N> __device__ __forceinline__ void cpwait(){
    asm volatile("cp.async.wait_group %0;\n" :: "n"(N));
}
__device__ __forceinline__ void mma8(float c[4],
        uint32_t a0,uint32_t a1,uint32_t a2,uint32_t a3,
        uint32_t b0,uint32_t b1){
    asm volatile(
      "mma.sync.aligned.m16n8k8.row.col.f32.tf32.tf32.f32 "
      "{%0,%1,%2,%3},{%4,%5,%6,%7},{%8,%9},{%0,%1,%2,%3};\n"
      : "+f"(c[0]), "+f"(c[1]), "+f"(c[2]), "+f"(c[3])
      : "r"(a0), "r"(a1), "r"(a2), "r"(a3), "r"(b0), "r"(b1));
}

// ---------------- pre-round kernels (tf32 RNA) ----------------
__global__ void round3_kernel(const float4* __restrict__ a, const float4* __restrict__ b,
                              const float4* __restrict__ c, float4* __restrict__ oa,
                              float4* __restrict__ ob, float4* __restrict__ oc, int n4)
{
    int i = blockIdx.x*blockDim.x + threadIdx.x;
    if (i >= n4) return;
    const float4* s = (blockIdx.y==0) ? a : (blockIdx.y==1) ? b : c;
    float4* d       = (blockIdx.y==0) ? oa : (blockIdx.y==1) ? ob : oc;
    float4 v = s[i];
    v.x = tff(v.x); v.y = tff(v.y); v.z = tff(v.z); v.w = tff(v.w);
    d[i] = v;
}
__global__ void round4_kernel(const float4* __restrict__ a, const float4* __restrict__ b,
                              const float4* __restrict__ c, const float4* __restrict__ e,
                              float4* __restrict__ oa, float4* __restrict__ ob,
                              float4* __restrict__ oc, float4* __restrict__ oe, int n4)
{
    int i = blockIdx.x*blockDim.x + threadIdx.x;
    if (i >= n4) return;
    const float4* s = (blockIdx.y==0) ? a : (blockIdx.y==1) ? b : (blockIdx.y==2) ? c : e;
    float4* d       = (blockIdx.y==0) ? oa : (blockIdx.y==1) ? ob : (blockIdx.y==2) ? oc : oe;
    float4 v = s[i];
    v.x = tff(v.x); v.y = tff(v.y); v.z = tff(v.z); v.w = tff(v.w);
    d[i] = v;
}

// ---------------- GEMM: C[M,N] = X[M,K] @ W[N,K]^T + bias ----------------
// Pre-rounded tf32 operands, no cvt in inner loop.
// Block tile 256x128x32, 256 threads (8 warps, 4m x 2n), warp tile 64x64.
// 3-stage cp.async pipeline, ONE __syncthreads per k-tile.
// blockIdx.z selects one of up to 3 independent GEMMs (merged QKV launch).
// mode 0: dst[m*1024+n] = val (fp32)           (output projection)
// mode 1: head-split store to [B,H,S,64], scaled, tf32-rounded (QKV)
struct GemmArgs { const float* A; const float* W; const float* bias; float* dst; float scale; };

#define GEMM_SMEM_BYTES (3*(256+128)*36*4)

__global__ void __launch_bounds__(256,1) gemm_tf32(
    GemmArgs ga0, GemmArgs ga1, GemmArgs ga2, int mode)
{
    extern __shared__ float sm[];
    float* sA = sm;                 // [3][256][36]
    float* sB = sm + 3*256*36;      // [3][128][36]
    const int tid = threadIdx.x;
    const int m0 = blockIdx.y << 8, n0 = blockIdx.x << 7;

    GemmArgs ga = (blockIdx.z==0) ? ga0 : (blockIdx.z==1) ? ga1 : ga2;
    const float* __restrict__ A = ga.A;
    const float* __restrict__ W = ga.W;

    auto load_tile = [&](int buf, int kt){
        const float* Ag = A + (size_t)m0*DMODEL + kt*32;
        const float* Wg = W + (size_t)n0*DMODEL + kt*32;
        float* a = sA + buf*(256*36);
        float* b = sB + buf*(128*36);
#pragma unroll
        for (int i = 0; i < 8; ++i){
            int v = i*256 + tid;
            int r = v >> 3, c = (v & 7) << 2;
            cp16(saddr(a + r*36 + c), Ag + (size_t)r*DMODEL + c);
        }
#pragma unroll
        for (int i = 0; i < 4; ++i){
            int v = i*256 + tid;
            int r = v >> 3, c = (v & 7) << 2;
            cp16(saddr(b + r*36 + c), Wg + (size_t)r*DMODEL + c);
        }
        cpcommit();
    };

    float acc[4][8][4];
#pragma unroll
    for (int i=0;i<4;i++)
#pragma unroll
        for (int j=0;j<8;j++)
#pragma unroll
            for (int e=0;e<4;e++) acc[i][j][e] = 0.f;

    load_tile(0, 0);
    load_tile(1, 1);

    const int warp = tid >> 5, lane = tid & 31;
    const int wm = warp >> 1, wn = warp & 1;
    const int g = lane >> 2, tig = lane & 3;

    for (int kt = 0; kt < 32; ++kt){
        if (kt == 31) cpwait<0>(); else cpwait<1>();
        __syncthreads();                 // tile kt visible to all; frees buf (kt+2)%3
        if (kt < 30) load_tile((kt+2)%3, kt+2);

        const float* a = sA + (kt%3)*(256*36);
        const float* b = sB + (kt%3)*(128*36);
#pragma unroll
        for (int ks = 0; ks < 4; ++ks){
            uint32_t af[4][4];
#pragma unroll
            for (int mt = 0; mt < 4; ++mt){
                int r = wm*64 + mt*16 + g;
                int c = ks*8 + tig;
                af[mt][0] = __float_as_uint(a[r*36 + c]);
                af[mt][1] = __float_as_uint(a[(r+8)*36 + c]);
                af[mt][2] = __float_as_uint(a[r*36 + c + 4]);
                af[mt][3] = __float_as_uint(a[(r+8)*36 + c + 4]);
            }
#pragma unroll
            for (int nt = 0; nt < 8; ++nt){
                int n = wn*64 + nt*8 + g;
                int c = ks*8 + tig;
                uint32_t b0 = __float_as_uint(b[n*36 + c]);
                uint32_t b1 = __float_as_uint(b[n*36 + c + 4]);
#pragma unroll
                for (int mt = 0; mt < 4; ++mt)
                    mma8(acc[mt][nt], af[mt][0],af[mt][1],af[mt][2],af[mt][3], b0,b1);
            }
        }
    }

    // epilogue
    const float* bias = ga.bias;
    float* dst = ga.dst;
    float scale = ga.scale;
#pragma unroll
    for (int mt = 0; mt < 4; ++mt){
#pragma unroll
        for (int nt = 0; nt < 8; ++nt){
            int row = m0 + wm*64 + mt*16 + g;
            int col = n0 + wn*64 + nt*8 + 2*tig;
#pragma unroll
            for (int half = 0; half < 2; ++half){
                int r = row + half*8;
                float v0 = (acc[mt][nt][2*half+0] + bias[col])   * scale;
                float v1 = (acc[mt][nt][2*half+1] + bias[col+1]) * scale;
                if (mode == 0){
                    *(float2*)(dst + (size_t)r*DMODEL + col) = make_float2(v0, v1);
                } else {
                    int bb = r >> 11, s = r & 2047, h = col >> 6, d = col & 63;
                    *(float2*)(dst + (((size_t)(bb*NHEAD + h))*SEQ + s)*DK + d) =
                        make_float2(tff(v0), tff(v1));
                }
            }
        }
    }
}

// ---------------- Flash attention ----------------
// per (b,h), 128-row Q tiles, 8 warps x 16 rows (softmax warp-private).
// K/V chunks of 64 keys, 3-stage cp.async pipeline, ONE __syncthreads per chunk.
// log2-domain online softmax (log2e folded into Q scale).
#define CH   64
#define NCH  (SEQ/CH)   // 32
#define ATTN_SMEM_BYTES ((3*CH*68 + 3*CH*72 + 8*16*68)*4)

__global__ void __launch_bounds__(256,1) attn_kernel()
{
    extern __shared__ float sm[];
    float* sK = sm;                             // [3][64][68]
    float* sV = sm + 3*CH*68;                   // [3][64][72]
    float* sP = sm + 3*CH*68 + 3*CH*72;         // [8][16][68]; also Q staging [128][68]

    const int tid  = threadIdx.x;
    const int warp = tid >> 5, lane = tid & 31;
    const int g = lane >> 2, tig = lane & 3;
    const int qt = blockIdx.x, bh = blockIdx.y;

    const float* qg  = g_q + ((size_t)bh*SEQ + qt*128)*DK;  // pre-scaled by log2e/8
    const float* kg0 = g_k + (size_t)bh*SEQ*DK;
    const float* vg0 = g_v + (size_t)bh*SEQ*DK;

    auto load_kv = [&](int buf, int kt){
        const float* kg = kg0 + (size_t)kt*CH*DK;
        const float* vg = vg0 + (size_t)kt*CH*DK;
        float* kb = sK + buf*(CH*68);
        float* vb = sV + buf*(CH*72);
#pragma unroll
        for (int i = 0; i < 4; ++i){
            int v = i*256 + tid;
            int r = v >> 4, c = (v & 15) << 2;
            cp16(saddr(kb + r*68 + c), kg + (size_t)r*DK + c);
            cp16(saddr(vb + r*72 + c), vg + (size_t)r*DK + c);
        }
        cpcommit();
    };

    // prologue: stage Q (own group), then KV chunks 0 and 1
#pragma unroll
    for (int i = 0; i < 8; ++i){
        int v = i*256 + tid;
        int r = v >> 4, c = (v & 15) << 2;
        cp16(saddr(sP + r*68 + c), qg + (size_t)r*DK + c);
    }
    cpcommit();
    load_kv(0, 0);
    load_kv(1, 1);
    cpwait<2>();            // Q group done
    __syncthreads();

    uint32_t qa[8][4];
#pragma unroll
    for (int kk = 0; kk < 8; ++kk){
        int r = warp*16 + g;
        int c = kk*8 + tig;
        qa[kk][0] = __float_as_uint(sP[r*68 + c]);
        qa[kk][1] = __float_as_uint(sP[(r+8)*68 + c]);
        qa[kk][2] = __float_as_uint(sP[r*68 + c + 4]);
        qa[kk][3] = __float_as_uint(sP[(r+8)*68 + c + 4]);
    }

    float o[8][4];
#pragma unroll
    for (int j=0;j<8;j++)
#pragma unroll
        for (int e=0;e<4;e++) o[j][e] = 0.f;
    float rm0 = -1e30f, rm1 = -1e30f, rl0 = 0.f, rl1 = 0.f;

    float* myP = sP + warp*(16*68);

    for (int kt = 0; kt < NCH; ++kt){
        if (kt == NCH-1) cpwait<0>(); else cpwait<1>();
        __syncthreads();    // chunk kt visible everywhere; frees buf (kt+2)%3
                            // (at kt=0 also: all warps have read qa / Q staging)
        if (kt < NCH-2) load_kv((kt+2)%3, kt+2);

        const float* kb = sK + (kt%3)*(CH*68);
        const float* vb = sV + (kt%3)*(CH*72);

        // S[16 x 64] = q @ K^T  (q pre-scaled by log2e/sqrt(dk))
        float s[8][4];
#pragma unroll
        for (int j=0;j<8;j++)
#pragma unroll
            for (int e=0;e<4;e++) s[j][e] = 0.f;
#pragma unroll
        for (int kk = 0; kk < 8; ++kk){
#pragma unroll
            for (int nt = 0; nt < 8; ++nt){
                int n = nt*8 + g;
                int c = kk*8 + tig;
                uint32_t b0 = __float_as_uint(kb[n*68 + c]);
                uint32_t b1 = __float_as_uint(kb[n*68 + c + 4]);
                mma8(s[nt], qa[kk][0],qa[kk][1],qa[kk][2],qa[kk][3], b0,b1);
            }
        }

        // online softmax in log2 domain (rows g, g+8 private to this warp)
        float m0c = -1e30f, m1c = -1e30f;
#pragma unroll
        for (int nt = 0; nt < 8; ++nt){
            m0c = fmaxf(m0c, fmaxf(s[nt][0], s[nt][1]));
            m1c = fmaxf(m1c, fmaxf(s[nt][2], s[nt][3]));
        }
        m0c = fmaxf(m0c, __shfl_xor_sync(0xffffffffu, m0c, 1));
        m0c = fmaxf(m0c, __shfl_xor_sync(0xffffffffu, m0c, 2));
        m1c = fmaxf(m1c, __shfl_xor_sync(0xffffffffu, m1c, 1));
        m1c = fmaxf(m1c, __shfl_xor_sync(0xffffffffu, m1c, 2));
        float nm0 = fmaxf(rm0, m0c), nm1 = fmaxf(rm1, m1c);
        float cor0 = exp2f(rm0 - nm0), cor1 = exp2f(rm1 - nm1);
        rm0 = nm0; rm1 = nm1;

        float l0 = 0.f, l1 = 0.f;
#pragma unroll
        for (int nt = 0; nt < 8; ++nt){
            float p0 = exp2f(s[nt][0] - nm0);
            float p1 = exp2f(s[nt][1] - nm0);
            float p2 = exp2f(s[nt][2] - nm1);
            float p3 = exp2f(s[nt][3] - nm1);
            l0 += p0 + p1; l1 += p2 + p3;
            *(float2*)(myP + g*68     + nt*8 + 2*tig) = make_float2(tff(p0), tff(p1));
            *(float2*)(myP + (g+8)*68 + nt*8 + 2*tig) = make_float2(tff(p2), tff(p3));
        }
        l0 += __shfl_xor_sync(0xffffffffu, l0, 1);
        l0 += __shfl_xor_sync(0xffffffffu, l0, 2);
        l1 += __shfl_xor_sync(0xffffffffu, l1, 1);
        l1 += __shfl_xor_sync(0xffffffffu, l1, 2);
        rl0 = rl0*cor0 + l0;
        rl1 = rl1*cor1 + l1;

#pragma unroll
        for (int j = 0; j < 8; ++j){
            o[j][0]*=cor0; o[j][1]*=cor0; o[j][2]*=cor1; o[j][3]*=cor1;
        }
        __syncwarp();  // P writes visible to warp

        // O += P @ V
#pragma unroll
        for (int kk = 0; kk < 8; ++kk){
            int c = kk*8 + tig;
            uint32_t a0 = __float_as_uint(myP[g*68 + c]);
            uint32_t a1 = __float_as_uint(myP[(g+8)*68 + c]);
            uint32_t a2 = __float_as_uint(myP[g*68 + c + 4]);
            uint32_t a3 = __float_as_uint(myP[(g+8)*68 + c + 4]);
#pragma unroll
            for (int nt = 0; nt < 8; ++nt){
                uint32_t b0 = __float_as_uint(vb[c*72 + nt*8 + g]);
                uint32_t b1 = __float_as_uint(vb[(c+4)*72 + nt*8 + g]);
                mma8(o[nt], a0,a1,a2,a3, b0,b1);
            }
        }
        __syncwarp();  // done reading P before next chunk overwrites it
    }

    // normalize + write context [B,S,D], tf32-rounded (feeds final GEMM cvt-free)
    float il0 = 1.f/rl0, il1 = 1.f/rl1;
    int b = bh >> 4, h = bh & 15;
    int r0 = b*SEQ + qt*128 + warp*16 + g;
#pragma unroll
    for (int nt = 0; nt < 8; ++nt){
        int col = h*64 + nt*8 + 2*tig;
        *(float2*)(g_ctx + (size_t)r0*DMODEL + col) =
            make_float2(tff(o[nt][0]*il0), tff(o[nt][1]*il0));
        *(float2*)(g_ctx + (size_t)(r0+8)*DMODEL + col) =
            make_float2(tff(o[nt][2]*il1), tff(o[nt][3]*il1));
    }
}

// ---------------- launch ----------------
extern "C" void kernel_launch(void* const* d_in, const int* in_sizes, int n_in,
                              void* d_out, int out_size)
{
    const float* Xq = (const float*)d_in[0];
    const float* Xk = (const float*)d_in[1];
    const float* Xv = (const float*)d_in[2];
    const float* Wq = (const float*)d_in[3]; const float* bq = (const float*)d_in[4];
    const float* Wk = (const float*)d_in[5]; const float* bk = (const float*)d_in[6];
    const float* Wv = (const float*)d_in[7]; const float* bv = (const float*)d_in[8];
    const float* Wo = (const float*)d_in[9]; const float* bo = (const float*)d_in[10];
    float* out = (float*)d_out;

    void *gq, *gk, *gv, *gctx, *gxq, *gxk, *gxv, *gwq, *gwk, *gwv, *gwo;
    cudaGetSymbolAddress(&gq,  g_q);
    cudaGetSymbolAddress(&gk,  g_k);
    cudaGetSymbolAddress(&gv,  g_v);
    cudaGetSymbolAddress(&gctx, g_ctx);
    cudaGetSymbolAddress(&gxq, g_xq);
    cudaGetSymbolAddress(&gxk, g_xk);
    cudaGetSymbolAddress(&gxv, g_xv);
    cudaGetSymbolAddress(&gwq, g_wq);
    cudaGetSymbolAddress(&gwk, g_wk);
    cudaGetSymbolAddress(&gwv, g_wv);
    cudaGetSymbolAddress(&gwo, g_wo);

    cudaFuncSetAttribute(gemm_tf32,  cudaFuncAttributeMaxDynamicSharedMemorySize, GEMM_SMEM_BYTES);
    cudaFuncSetAttribute(attn_kernel, cudaFuncAttributeMaxDynamicSharedMemorySize, ATTN_SMEM_BYTES);

    // pre-round raw inputs to tf32 (RNA) once -> all GEMM inner loops cvt-free
    {
        int n4x = (MROWS*DMODEL)/4;
        dim3 gx((n4x + 255)/256, 3);
        round3_kernel<<<gx, 256>>>((const float4*)Xq, (const float4*)Xk, (const float4*)Xv,
                                   (float4*)gxq, (float4*)gxk, (float4*)gxv, n4x);
        int n4w = (DMODEL*DMODEL)/4;
        dim3 gw((n4w + 255)/256, 4);
        round4_kernel<<<gw, 256>>>((const float4*)Wq, (const float4*)Wk,
                                   (const float4*)Wv, (const float4*)Wo,
                                   (float4*)gwq, (float4*)gwk, (float4*)gwv, (float4*)gwo, n4w);
    }

    const float qscale = 0.125f * 1.4426950408889634f;   // 1/sqrt(dk) * log2(e)
    GemmArgs aq{(const float*)gxq, (const float*)gwq, bq, (float*)gq, qscale};
    GemmArgs ak{(const float*)gxk, (const float*)gwk, bk, (float*)gk, 1.0f};
    GemmArgs av{(const float*)gxv, (const float*)gwv, bv, (float*)gv, 1.0f};
    GemmArgs ao{(const float*)gctx, (const float*)gwo, bo, out, 1.0f};

    // merged QKV: one launch, grid.z selects projection (768 CTAs, better wave packing)
    dim3 gqkv(DMODEL/128, MROWS/256, 3);
    gemm_tf32<<<gqkv, 256, GEMM_SMEM_BYTES>>>(aq, ak, av, 1);

    attn_kernel<<<dim3(SEQ/128, BATCH*NHEAD), 256, ATTN_SMEM_BYTES>>>();

    dim3 go(DMODEL/128, MROWS/256, 1);
    gemm_tf32<<<go, 256, GEMM_SMEM_BYTES>>>(ao, ao, ao, 0);
}

// round 4
// speedup vs baseline: 1.0900x; 1.0900x over previous
#include <cuda_runtime.h>
#include <cstdint>

#define SEQ    2048
#define BATCH  4
#define NHEAD  16
#define DK     64
#define DMODEL 1024
#define MROWS  (BATCH*SEQ)

// Scratch (allocation-free rule: device globals).
__device__ float g_q[BATCH*NHEAD*SEQ*DK];
__device__ float g_k[BATCH*NHEAD*SEQ*DK];
__device__ float g_v[BATCH*NHEAD*SEQ*DK];
__device__ float g_ctx[(size_t)MROWS*DMODEL];
// tf32-pre-rounded copies of raw inputs
__device__ float g_xq[(size_t)MROWS*DMODEL];
__device__ float g_xk[(size_t)MROWS*DMODEL];
__device__ float g_xv[(size_t)MROWS*DMODEL];
__device__ float g_wq[DMODEL*DMODEL];
__device__ float g_wk[DMODEL*DMODEL];
__device__ float g_wv[DMODEL*DMODEL];
__device__ float g_wo[DMODEL*DMODEL];

// ---------------- helpers ----------------
__device__ __forceinline__ uint32_t f2tf(float x){
    uint32_t r; asm("cvt.rna.tf32.f32 %0, %1;" : "=r"(r) : "f"(x)); return r;
}
__device__ __forceinline__ float tff(float x){ return __uint_as_float(f2tf(x)); }
__device__ __forceinline__ uint32_t saddr(const void* p){
    return (uint32_t)__cvta_generic_to_shared(p);
}
__device__ __forceinline__ void cp16(uint32_t s, const void* g){
    asm volatile("cp.async.cg.shared.global [%0], [%1], 16;\n" :: "r"(s), "l"(g));
}
__device__ __forceinline__ void cpcommit(){ asm volatile("cp.async.commit_group;\n"); }
template<int N> __device__ __forceinline__ void cpwait(){
    asm volatile("cp.async.wait_group %0;\n" :: "n"(N));
}
__device__ __forceinline__ void mma8(float c[4],
        uint32_t a0,uint32_t a1,uint32_t a2,uint32_t a3,
        uint32_t b0,uint32_t b1){
    asm volatile(
      "mma.sync.aligned.m16n8k8.row.col.f32.tf32.tf32.f32 "
      "{%0,%1,%2,%3},{%4,%5,%6,%7},{%8,%9},{%0,%1,%2,%3};\n"
      : "+f"(c[0]), "+f"(c[1]), "+f"(c[2]), "+f"(c[3])
      : "r"(a0), "r"(a1), "r"(a2), "r"(a3), "r"(b0), "r"(b1));
}

// ---------------- pre-round kernels (tf32 RNA) ----------------
__global__ void round3_kernel(const float4* __restrict__ a, const float4* __restrict__ b,
                              const float4* __restrict__ c, float4* __restrict__ oa,
                              float4* __restrict__ ob, float4* __restrict__ oc, int n4)
{
    int i = blockIdx.x*blockDim.x + threadIdx.x;
    if (i >= n4) return;
    const float4* s = (blockIdx.y==0) ? a : (blockIdx.y==1) ? b : c;
    float4* d       = (blockIdx.y==0) ? oa : (blockIdx.y==1) ? ob : oc;
    float4 v = s[i];
    v.x = tff(v.x); v.y = tff(v.y); v.z = tff(v.z); v.w = tff(v.w);
    d[i] = v;
}
__global__ void round4_kernel(const float4* __restrict__ a, const float4* __restrict__ b,
                              const float4* __restrict__ c, const float4* __restrict__ e,
                              float4* __restrict__ oa, float4* __restrict__ ob,
                              float4* __restrict__ oc, float4* __restrict__ oe, int n4)
{
    int i = blockIdx.x*blockDim.x + threadIdx.x;
    if (i >= n4) return;
    const float4* s = (blockIdx.y==0) ? a : (blockIdx.y==1) ? b : (blockIdx.y==2) ? c : e;
    float4* d       = (blockIdx.y==0) ? oa : (blockIdx.y==1) ? ob : (blockIdx.y==2) ? oc : oe;
    float4 v = s[i];
    v.x = tff(v.x); v.y = tff(v.y); v.z = tff(v.z); v.w = tff(v.w);
    d[i] = v;
}

// ---------------- GEMM (unchanged from R3): C = X @ W^T + bias ----------------
struct GemmArgs { const float* A; const float* W; const float* bias; float* dst; float scale; };

#define GEMM_SMEM_BYTES (3*(256+128)*36*4)

__global__ void __launch_bounds__(256,1) gemm_tf32(
    GemmArgs ga0, GemmArgs ga1, GemmArgs ga2, int mode)
{
    extern __shared__ float sm[];
    float* sA = sm;                 // [3][256][36]
    float* sB = sm + 3*256*36;      // [3][128][36]
    const int tid = threadIdx.x;
    const int m0 = blockIdx.y << 8, n0 = blockIdx.x << 7;

    GemmArgs ga = (blockIdx.z==0) ? ga0 : (blockIdx.z==1) ? ga1 : ga2;
    const float* __restrict__ A = ga.A;
    const float* __restrict__ W = ga.W;

    auto load_tile = [&](int buf, int kt){
        const float* Ag = A + (size_t)m0*DMODEL + kt*32;
        const float* Wg = W + (size_t)n0*DMODEL + kt*32;
        float* a = sA + buf*(256*36);
        float* b = sB + buf*(128*36);
#pragma unroll
        for (int i = 0; i < 8; ++i){
            int v = i*256 + tid;
            int r = v >> 3, c = (v & 7) << 2;
            cp16(saddr(a + r*36 + c), Ag + (size_t)r*DMODEL + c);
        }
#pragma unroll
        for (int i = 0; i < 4; ++i){
            int v = i*256 + tid;
            int r = v >> 3, c = (v & 7) << 2;
            cp16(saddr(b + r*36 + c), Wg + (size_t)r*DMODEL + c);
        }
        cpcommit();
    };

    float acc[4][8][4];
#pragma unroll
    for (int i=0;i<4;i++)
#pragma unroll
        for (int j=0;j<8;j++)
#pragma unroll
            for (int e=0;e<4;e++) acc[i][j][e] = 0.f;

    load_tile(0, 0);
    load_tile(1, 1);

    const int warp = tid >> 5, lane = tid & 31;
    const int wm = warp >> 1, wn = warp & 1;
    const int g = lane >> 2, tig = lane & 3;

    for (int kt = 0; kt < 32; ++kt){
        if (kt == 31) cpwait<0>(); else cpwait<1>();
        __syncthreads();
        if (kt < 30) load_tile((kt+2)%3, kt+2);

        const float* a = sA + (kt%3)*(256*36);
        const float* b = sB + (kt%3)*(128*36);
#pragma unroll
        for (int ks = 0; ks < 4; ++ks){
            uint32_t af[4][4];
#pragma unroll
            for (int mt = 0; mt < 4; ++mt){
                int r = wm*64 + mt*16 + g;
                int c = ks*8 + tig;
                af[mt][0] = __float_as_uint(a[r*36 + c]);
                af[mt][1] = __float_as_uint(a[(r+8)*36 + c]);
                af[mt][2] = __float_as_uint(a[r*36 + c + 4]);
                af[mt][3] = __float_as_uint(a[(r+8)*36 + c + 4]);
            }
#pragma unroll
            for (int nt = 0; nt < 8; ++nt){
                int n = wn*64 + nt*8 + g;
                int c = ks*8 + tig;
                uint32_t b0 = __float_as_uint(b[n*36 + c]);
                uint32_t b1 = __float_as_uint(b[n*36 + c + 4]);
#pragma unroll
                for (int mt = 0; mt < 4; ++mt)
                    mma8(acc[mt][nt], af[mt][0],af[mt][1],af[mt][2],af[mt][3], b0,b1);
            }
        }
    }

    const float* bias = ga.bias;
    float* dst = ga.dst;
    float scale = ga.scale;
#pragma unroll
    for (int mt = 0; mt < 4; ++mt){
#pragma unroll
        for (int nt = 0; nt < 8; ++nt){
            int row = m0 + wm*64 + mt*16 + g;
            int col = n0 + wn*64 + nt*8 + 2*tig;
#pragma unroll
            for (int half = 0; half < 2; ++half){
                int r = row + half*8;
                float v0 = (acc[mt][nt][2*half+0] + bias[col])   * scale;
                float v1 = (acc[mt][nt][2*half+1] + bias[col+1]) * scale;
                if (mode == 0){
                    *(float2*)(dst + (size_t)r*DMODEL + col) = make_float2(v0, v1);
                } else {
                    int bb = r >> 11, s = r & 2047, h = col >> 6, d = col & 63;
                    *(float2*)(dst + (((size_t)(bb*NHEAD + h))*SEQ + s)*DK + d) =
                        make_float2(tff(v0), tff(v1));
                }
            }
        }
    }
}

// ---------------- Flash attention v2 ----------------
// 128-thread CTAs (4 warps x 32 Q rows = 128 rows), 2 CTAs/SM.
// mt=2: each K/V B-fragment feeds 2 MMAs (LDS:MMA = 1.0).
// P never goes to smem: S-accumulator -> A-fragment via quad shuffles.
// 3-stage cp.async K/V pipeline, one barrier per 64-key chunk.
#define CH   64
#define NCH  (SEQ/CH)   // 32
#define ATTN_SMEM_BYTES ((3*CH*68 + 3*CH*72)*4)   // 107,520 B -> 2 CTAs/SM

__global__ void __launch_bounds__(128,2) attn_kernel()
{
    extern __shared__ float sm[];
    float* sK = sm;              // [3][64][68]
    float* sV = sm + 3*CH*68;    // [3][64][72]

    const int tid  = threadIdx.x;
    const int warp = tid >> 5, lane = tid & 31;
    const int g = lane >> 2, tig = lane & 3;
    const int qt = blockIdx.x, bh = blockIdx.y;

    const float* qg  = g_q + ((size_t)bh*SEQ + qt*128)*DK;  // pre-scaled by log2e/8
    const float* kg0 = g_k + (size_t)bh*SEQ*DK;
    const float* vg0 = g_v + (size_t)bh*SEQ*DK;

    auto load_kv = [&](int buf, int kt){
        const float* kg = kg0 + (size_t)kt*CH*DK;
        const float* vg = vg0 + (size_t)kt*CH*DK;
        float* kb = sK + buf*(CH*68);
        float* vb = sV + buf*(CH*72);
#pragma unroll
        for (int i = 0; i < 8; ++i){
            int v = i*128 + tid;
            int r = v >> 4, c = (v & 15) << 2;
            cp16(saddr(kb + r*68 + c), kg + (size_t)r*DK + c);
            cp16(saddr(vb + r*72 + c), vg + (size_t)r*DK + c);
        }
        cpcommit();
    };

    load_kv(0, 0);
    load_kv(1, 1);

    // Q fragments straight from gmem into registers (one-time, overlaps KV loads)
    uint32_t qa[2][8][4];
    {
        const int r0 = warp*32 + g;
#pragma unroll
        for (int mt = 0; mt < 2; ++mt)
#pragma unroll
        for (int kk = 0; kk < 8; ++kk){
            int r = r0 + mt*16;
            int c = kk*8 + tig;
            qa[mt][kk][0] = __float_as_uint(qg[(size_t)r*DK + c]);
            qa[mt][kk][1] = __float_as_uint(qg[(size_t)(r+8)*DK + c]);
            qa[mt][kk][2] = __float_as_uint(qg[(size_t)r*DK + c + 4]);
            qa[mt][kk][3] = __float_as_uint(qg[(size_t)(r+8)*DK + c + 4]);
        }
    }

    float o[2][8][4];
#pragma unroll
    for (int i=0;i<2;i++)
#pragma unroll
        for (int j=0;j<8;j++)
#pragma unroll
            for (int e=0;e<4;e++) o[i][j][e] = 0.f;
    float rm[2][2] = {{-1e30f,-1e30f},{-1e30f,-1e30f}};
    float rl[2][2] = {{0.f,0.f},{0.f,0.f}};

    const unsigned FULL = 0xffffffffu;
    const int lo_lane = (lane & ~3) | (tig >> 1);
    const int hi_lane = lo_lane + 2;

    for (int kt = 0; kt < NCH; ++kt){
        if (kt == NCH-1) cpwait<0>(); else cpwait<1>();
        __syncthreads();                      // chunk kt visible; buf (kt+2)%3 free
        if (kt < NCH-2) load_kv((kt+2)%3, kt+2);

        const float* kb = sK + (kt%3)*(CH*68);
        const float* vb = sV + (kt%3)*(CH*72);

        // S[32 x 64] = q @ K^T  (both m-tiles share every K B-fragment)
        float s[2][8][4];
#pragma unroll
        for (int i=0;i<2;i++)
#pragma unroll
            for (int j=0;j<8;j++)
#pragma unroll
                for (int e=0;e<4;e++) s[i][j][e] = 0.f;
#pragma unroll
        for (int kk = 0; kk < 8; ++kk){
#pragma unroll
            for (int nt = 0; nt < 8; ++nt){
                int n = nt*8 + g;
                int c = kk*8 + tig;
                uint32_t b0 = __float_as_uint(kb[n*68 + c]);
                uint32_t b1 = __float_as_uint(kb[n*68 + c + 4]);
                mma8(s[0][nt], qa[0][kk][0],qa[0][kk][1],qa[0][kk][2],qa[0][kk][3], b0,b1);
                mma8(s[1][nt], qa[1][kk][0],qa[1][kk][1],qa[1][kk][2],qa[1][kk][3], b0,b1);
            }
        }

        // online softmax in log2 domain (rows private to warp); P tf32-rounded in place
#pragma unroll
        for (int mt = 0; mt < 2; ++mt){
            float m0 = -1e30f, m1 = -1e30f;
#pragma unroll
            for (int nt = 0; nt < 8; ++nt){
                m0 = fmaxf(m0, fmaxf(s[mt][nt][0], s[mt][nt][1]));
                m1 = fmaxf(m1, fmaxf(s[mt][nt][2], s[mt][nt][3]));
            }
            m0 = fmaxf(m0, __shfl_xor_sync(FULL, m0, 1));
            m0 = fmaxf(m0, __shfl_xor_sync(FULL, m0, 2));
            m1 = fmaxf(m1, __shfl_xor_sync(FULL, m1, 1));
            m1 = fmaxf(m1, __shfl_xor_sync(FULL, m1, 2));
            float nm0 = fmaxf(rm[mt][0], m0), nm1 = fmaxf(rm[mt][1], m1);
            float cor0 = exp2f(rm[mt][0] - nm0), cor1 = exp2f(rm[mt][1] - nm1);
            rm[mt][0] = nm0; rm[mt][1] = nm1;

            float l0 = 0.f, l1 = 0.f;
#pragma unroll
            for (int nt = 0; nt < 8; ++nt){
                float p0 = tff(exp2f(s[mt][nt][0] - nm0));
                float p1 = tff(exp2f(s[mt][nt][1] - nm0));
                float p2 = tff(exp2f(s[mt][nt][2] - nm1));
                float p3 = tff(exp2f(s[mt][nt][3] - nm1));
                s[mt][nt][0] = p0; s[mt][nt][1] = p1;
                s[mt][nt][2] = p2; s[mt][nt][3] = p3;
                l0 += p0 + p1; l1 += p2 + p3;
            }
            l0 += __shfl_xor_sync(FULL, l0, 1);
            l0 += __shfl_xor_sync(FULL, l0, 2);
            l1 += __shfl_xor_sync(FULL, l1, 1);
            l1 += __shfl_xor_sync(FULL, l1, 2);
            rl[mt][0] = rl[mt][0]*cor0 + l0;
            rl[mt][1] = rl[mt][1]*cor1 + l1;
#pragma unroll
            for (int nt = 0; nt < 8; ++nt){
                o[mt][nt][0] *= cor0; o[mt][nt][1] *= cor0;
                o[mt][nt][2] *= cor1; o[mt][nt][3] *= cor1;
            }
        }

        // O += P @ V; P A-fragments built by quad shuffles from the S accumulator
#pragma unroll
        for (int kk = 0; kk < 8; ++kk){
            uint32_t aP[2][4];
#pragma unroll
            for (int mt = 0; mt < 2; ++mt){
                float v0l = __shfl_sync(FULL, s[mt][kk][0], lo_lane);
                float v1l = __shfl_sync(FULL, s[mt][kk][1], lo_lane);
                float v2l = __shfl_sync(FULL, s[mt][kk][2], lo_lane);
                float v3l = __shfl_sync(FULL, s[mt][kk][3], lo_lane);
                float v0h = __shfl_sync(FULL, s[mt][kk][0], hi_lane);
                float v1h = __shfl_sync(FULL, s[mt][kk][1], hi_lane);
                float v2h = __shfl_sync(FULL, s[mt][kk][2], hi_lane);
                float v3h = __shfl_sync(FULL, s[mt][kk][3], hi_lane);
                bool odd = (tig & 1);
                aP[mt][0] = __float_as_uint(odd ? v1l : v0l);
                aP[mt][1] = __float_as_uint(odd ? v3l : v2l);
                aP[mt][2] = __float_as_uint(odd ? v1h : v0h);
                aP[mt][3] = __float_as_uint(odd ? v3h : v2h);
            }
#pragma unroll
            for (int nt = 0; nt < 8; ++nt){
                int c = kk*8 + tig;
                uint32_t b0 = __float_as_uint(vb[c*72 + nt*8 + g]);
                uint32_t b1 = __float_as_uint(vb[(c+4)*72 + nt*8 + g]);
                mma8(o[0][nt], aP[0][0],aP[0][1],aP[0][2],aP[0][3], b0,b1);
                mma8(o[1][nt], aP[1][0],aP[1][1],aP[1][2],aP[1][3], b0,b1);
            }
        }
    }

    // normalize + write context [B,S,D], tf32-rounded (feeds final GEMM cvt-free)
    int b = bh >> 4, h = bh & 15;
#pragma unroll
    for (int mt = 0; mt < 2; ++mt){
        float il0 = 1.f/rl[mt][0], il1 = 1.f/rl[mt][1];
        int r0 = b*SEQ + qt*128 + warp*32 + mt*16 + g;
#pragma unroll
        for (int nt = 0; nt < 8; ++nt){
            int col = h*64 + nt*8 + 2*tig;
            *(float2*)(g_ctx + (size_t)r0*DMODEL + col) =
                make_float2(tff(o[mt][nt][0]*il0), tff(o[mt][nt][1]*il0));
            *(float2*)(g_ctx + (size_t)(r0+8)*DMODEL + col) =
                make_float2(tff(o[mt][nt][2]*il1), tff(o[mt][nt][3]*il1));
        }
    }
}

// ---------------- launch ----------------
extern "C" void kernel_launch(void* const* d_in, const int* in_sizes, int n_in,
                              void* d_out, int out_size)
{
    const float* Xq = (const float*)d_in[0];
    const float* Xk = (const float*)d_in[1];
    const float* Xv = (const float*)d_in[2];
    const float* Wq = (const float*)d_in[3]; const float* bq = (const float*)d_in[4];
    const float* Wk = (const float*)d_in[5]; const float* bk = (const float*)d_in[6];
    const float* Wv = (const float*)d_in[7]; const float* bv = (const float*)d_in[8];
    const float* Wo = (const float*)d_in[9]; const float* bo = (const float*)d_in[10];
    float* out = (float*)d_out;

    void *gq, *gk, *gv, *gctx, *gxq, *gxk, *gxv, *gwq, *gwk, *gwv, *gwo;
    cudaGetSymbolAddress(&gq,  g_q);
    cudaGetSymbolAddress(&gk,  g_k);
    cudaGetSymbolAddress(&gv,  g_v);
    cudaGetSymbolAddress(&gctx, g_ctx);
    cudaGetSymbolAddress(&gxq, g_xq);
    cudaGetSymbolAddress(&gxk, g_xk);
    cudaGetSymbolAddress(&gxv, g_xv);
    cudaGetSymbolAddress(&gwq, g_wq);
    cudaGetSymbolAddress(&gwk, g_wk);
    cudaGetSymbolAddress(&gwv, g_wv);
    cudaGetSymbolAddress(&gwo, g_wo);

    cudaFuncSetAttribute(gemm_tf32,  cudaFuncAttributeMaxDynamicSharedMemorySize, GEMM_SMEM_BYTES);
    cudaFuncSetAttribute(attn_kernel, cudaFuncAttributeMaxDynamicSharedMemorySize, ATTN_SMEM_BYTES);

    // pre-round raw inputs to tf32 (RNA) once -> all GEMM inner loops cvt-free
    {
        int n4x = (MROWS*DMODEL)/4;
        dim3 gx((n4x + 255)/256, 3);
        round3_kernel<<<gx, 256>>>((const float4*)Xq, (const float4*)Xk, (const float4*)Xv,
                                   (float4*)gxq, (float4*)gxk, (float4*)gxv, n4x);
        int n4w = (DMODEL*DMODEL)/4;
        dim3 gw((n4w + 255)/256, 4);
        round4_kernel<<<gw, 256>>>((const float4*)Wq, (const float4*)Wk,
                                   (const float4*)Wv, (const float4*)Wo,
                                   (float4*)gwq, (float4*)gwk, (float4*)gwv, (float4*)gwo, n4w);
    }

    const float qscale = 0.125f * 1.4426950408889634f;   // 1/sqrt(dk) * log2(e)
    GemmArgs aq{(const float*)gxq, (const float*)gwq, bq, (float*)gq, qscale};
    GemmArgs ak{(const float*)gxk, (const float*)gwk, bk, (float*)gk, 1.0f};
    GemmArgs av{(const float*)gxv, (const float*)gwv, bv, (float*)gv, 1.0f};
    GemmArgs ao{(const float*)gctx, (const float*)gwo, bo, out, 1.0f};

    dim3 gqkv(DMODEL/128, MROWS/256, 3);
    gemm_tf32<<<gqkv, 256, GEMM_SMEM_BYTES>>>(aq, ak, av, 1);

    attn_kernel<<<dim3(SEQ/128, BATCH*NHEAD), 128, ATTN_SMEM_BYTES>>>();

    dim3 go(DMODEL/128, MROWS/256, 1);
    gemm_tf32<<<go, 256, GEMM_SMEM_BYTES>>>(ao, ao, ao, 0);
}

// round 5
// speedup vs baseline: 2.0182x; 1.8515x over previous
#include <cuda_runtime.h>
#include <cuda_fp16.h>
#include <cstdint>

#define SEQ    2048
#define BATCH  4
#define NHEAD  16
#define DK     64
#define DMODEL 1024
#define MROWS  (BATCH*SEQ)

// Scratch (allocation-free rule: device globals). All fp16 now.
__device__ __half g_q[BATCH*NHEAD*SEQ*DK];     // [b,h,s,d], pre-scaled by log2e/8
__device__ __half g_k[BATCH*NHEAD*SEQ*DK];     // [b,h,s,d]
__device__ __half g_vt[BATCH*NHEAD*DK*SEQ];    // [b,h,d,s]  (transposed!)
__device__ __half g_ctx[(size_t)MROWS*DMODEL]; // [b*s, d_model]
// fp16 copies of raw inputs / weights
__device__ __half g_xq[(size_t)MROWS*DMODEL];
__device__ __half g_xk[(size_t)MROWS*DMODEL];
__device__ __half g_xv[(size_t)MROWS*DMODEL];
__device__ __half g_wq[DMODEL*DMODEL];
__device__ __half g_wk[DMODEL*DMODEL];
__device__ __half g_wv[DMODEL*DMODEL];
__device__ __half g_wo[DMODEL*DMODEL];

// ---------------- helpers ----------------
__device__ __forceinline__ uint32_t saddr(const void* p){
    return (uint32_t)__cvta_generic_to_shared(p);
}
__device__ __forceinline__ void cp16(uint32_t s, const void* g){
    asm volatile("cp.async.cg.shared.global [%0], [%1], 16;\n" :: "r"(s), "l"(g));
}
__device__ __forceinline__ void cpcommit(){ asm volatile("cp.async.commit_group;\n"); }
template<int N> __device__ __forceinline__ void cpwait(){
    asm volatile("cp.async.wait_group %0;\n" :: "n"(N));
}
// m16n8k16 fp16 MMA, row.col, fp32 accumulate (D==C in-place)
__device__ __forceinline__ void mma16(float c[4],
        uint32_t a0,uint32_t a1,uint32_t a2,uint32_t a3,
        uint32_t b0,uint32_t b1){
    asm volatile(
      "mma.sync.aligned.m16n8k16.row.col.f32.f16.f16.f32 "
      "{%0,%1,%2,%3},{%4,%5,%6,%7},{%8,%9},{%0,%1,%2,%3};\n"
      : "+f"(c[0]), "+f"(c[1]), "+f"(c[2]), "+f"(c[3])
      : "r"(a0), "r"(a1), "r"(a2), "r"(a3), "r"(b0), "r"(b1));
}
__device__ __forceinline__ uint32_t packh2(float lo, float hi){
    __half2 h = __floats2half2_rn(lo, hi);
    return *reinterpret_cast<uint32_t*>(&h);
}
__device__ __forceinline__ uint32_t ldu32(const __half* p){
    return *reinterpret_cast<const uint32_t*>(p);
}

// ---------------- convert kernels (fp32 -> fp16 RN) ----------------
__global__ void cvt3_kernel(const float4* __restrict__ a, const float4* __restrict__ b,
                            const float4* __restrict__ c, __half2* __restrict__ oa,
                            __half2* __restrict__ ob, __half2* __restrict__ oc, int n4)
{
    int i = blockIdx.x*blockDim.x + threadIdx.x;
    if (i >= n4) return;
    const float4* s = (blockIdx.y==0) ? a : (blockIdx.y==1) ? b : c;
    __half2* d      = (blockIdx.y==0) ? oa : (blockIdx.y==1) ? ob : oc;
    float4 v = s[i];
    d[2*i]   = __floats2half2_rn(v.x, v.y);
    d[2*i+1] = __floats2half2_rn(v.z, v.w);
}
__global__ void cvt4_kernel(const float4* __restrict__ a, const float4* __restrict__ b,
                            const float4* __restrict__ c, const float4* __restrict__ e,
                            __half2* __restrict__ oa, __half2* __restrict__ ob,
                            __half2* __restrict__ oc, __half2* __restrict__ oe, int n4)
{
    int i = blockIdx.x*blockDim.x + threadIdx.x;
    if (i >= n4) return;
    const float4* s = (blockIdx.y==0) ? a : (blockIdx.y==1) ? b : (blockIdx.y==2) ? c : e;
    __half2* d      = (blockIdx.y==0) ? oa : (blockIdx.y==1) ? ob : (blockIdx.y==2) ? oc : oe;
    float4 v = s[i];
    d[2*i]   = __floats2half2_rn(v.x, v.y);
    d[2*i+1] = __floats2half2_rn(v.z, v.w);
}

// ---------------- GEMM fp16: C[M,N] = X[M,K] @ W[N,K]^T + bias ----------------
// Block tile 256x128x64, 256 threads (8 warps as 4m x 2n), warp tile 64x64.
// 3-stage cp.async pipeline, one barrier per k-tile (16 k-tiles).
// mode 0: dst fp32 [m,1024]            (output projection)
// mode 1: dst fp16 [b,h,s,64], scaled  (q, k)
// mode 2: dst fp16 [b,h,64,s] TRANSPOSED (v)
struct GemmArgs { const __half* A; const __half* W; const float* bias;
                  void* dst; float scale; int mode; };

#define KT       64
#define GSTRIDE  72     // halves per smem row (64 + 8 pad)
#define GEMM_SMEM_BYTES (3*(256+128)*GSTRIDE*2)

__global__ void __launch_bounds__(256,1) gemm_fp16(GemmArgs ga0, GemmArgs ga1, GemmArgs ga2)
{
    extern __shared__ __half smh[];
    __half* sA = smh;                       // [3][256][72]
    __half* sB = smh + 3*256*GSTRIDE;       // [3][128][72]
    const int tid = threadIdx.x;
    const int m0 = blockIdx.y << 8, n0 = blockIdx.x << 7;

    GemmArgs ga = (blockIdx.z==0) ? ga0 : (blockIdx.z==1) ? ga1 : ga2;
    const __half* __restrict__ A = ga.A;
    const __half* __restrict__ W = ga.W;

    auto load_tile = [&](int buf, int kt){
        const __half* Ag = A + (size_t)m0*DMODEL + kt*KT;
        const __half* Wg = W + (size_t)n0*DMODEL + kt*KT;
        __half* a = sA + buf*(256*GSTRIDE);
        __half* b = sB + buf*(128*GSTRIDE);
#pragma unroll
        for (int i = 0; i < 8; ++i){
            int v = i*256 + tid;
            int r = v >> 3, c = (v & 7) << 3;
            cp16(saddr(a + r*GSTRIDE + c), Ag + (size_t)r*DMODEL + c);
        }
#pragma unroll
        for (int i = 0; i < 4; ++i){
            int v = i*256 + tid;
            int r = v >> 3, c = (v & 7) << 3;
            cp16(saddr(b + r*GSTRIDE + c), Wg + (size_t)r*DMODEL + c);
        }
        cpcommit();
    };

    float acc[4][8][4];
#pragma unroll
    for (int i=0;i<4;i++)
#pragma unroll
        for (int j=0;j<8;j++)
#pragma unroll
            for (int e=0;e<4;e++) acc[i][j][e] = 0.f;

    load_tile(0, 0);
    load_tile(1, 1);

    const int warp = tid >> 5, lane = tid & 31;
    const int wm = warp >> 1, wn = warp & 1;
    const int g = lane >> 2, tig = lane & 3;

    for (int kt = 0; kt < 16; ++kt){
        if (kt == 15) cpwait<0>(); else cpwait<1>();
        __syncthreads();
        if (kt < 14) load_tile((kt+2)%3, kt+2);

        const __half* a = sA + (kt%3)*(256*GSTRIDE);
        const __half* b = sB + (kt%3)*(128*GSTRIDE);
#pragma unroll
        for (int ks = 0; ks < 4; ++ks){      // 4 x k16
            uint32_t af[4][4];
#pragma unroll
            for (int mt = 0; mt < 4; ++mt){
                int r = wm*64 + mt*16 + g;
                int c = ks*16 + 2*tig;
                af[mt][0] = ldu32(a + r*GSTRIDE + c);
                af[mt][1] = ldu32(a + (r+8)*GSTRIDE + c);
                af[mt][2] = ldu32(a + r*GSTRIDE + c + 8);
                af[mt][3] = ldu32(a + (r+8)*GSTRIDE + c + 8);
            }
#pragma unroll
            for (int nt = 0; nt < 8; ++nt){
                int n = wn*64 + nt*8 + g;
                int c = ks*16 + 2*tig;
                uint32_t b0 = ldu32(b + n*GSTRIDE + c);
                uint32_t b1 = ldu32(b + n*GSTRIDE + c + 8);
#pragma unroll
                for (int mt = 0; mt < 4; ++mt)
                    mma16(acc[mt][nt], af[mt][0],af[mt][1],af[mt][2],af[mt][3], b0,b1);
            }
        }
    }

    // epilogue
    const float* bias = ga.bias;
    const float scale = ga.scale;
    const int mode = ga.mode;
#pragma unroll
    for (int mt = 0; mt < 4; ++mt){
#pragma unroll
        for (int nt = 0; nt < 8; ++nt){
            int row = m0 + wm*64 + mt*16 + g;
            int col = n0 + wn*64 + nt*8 + 2*tig;
#pragma unroll
            for (int half = 0; half < 2; ++half){
                int r = row + half*8;
                float v0 = (acc[mt][nt][2*half+0] + bias[col])   * scale;
                float v1 = (acc[mt][nt][2*half+1] + bias[col+1]) * scale;
                if (mode == 0){
                    *(float2*)((float*)ga.dst + (size_t)r*DMODEL + col) = make_float2(v0, v1);
                } else if (mode == 1){
                    int bb = r >> 11, s = r & 2047, h = col >> 6, d = col & 63;
                    *(__half2*)((__half*)ga.dst + (((size_t)(bb*NHEAD + h))*SEQ + s)*DK + d) =
                        __floats2half2_rn(v0, v1);
                } else {  // mode 2: V transposed [b,h,d,s]
                    int bb = r >> 11, s = r & 2047, h = col >> 6, d = col & 63;
                    __half* p = (__half*)ga.dst + (((size_t)(bb*NHEAD + h))*DK + d)*SEQ + s;
                    p[0]   = __float2half_rn(v0);
                    p[SEQ] = __float2half_rn(v1);
                }
            }
        }
    }
}

// ---------------- Flash attention fp16 ----------------
// 128-thread CTAs (4 warps x 32 Q rows), 2 CTAs/SM.
// m16n8k16: S accumulators pack DIRECTLY into P A-fragments (no shuffles).
// V is pre-transposed in gmem -> contiguous half2 B-fragments.
// 3-stage cp.async K/V pipeline, one barrier per 64-key chunk.
#define CH   64
#define NCH  (SEQ/CH)   // 32
#define ASTRIDE 72      // halves per smem row
#define ATTN_SMEM_BYTES (2*(3*CH*ASTRIDE + 3*DK*ASTRIDE))   // 55,296 B

__global__ void __launch_bounds__(128,2) attn_kernel()
{
    extern __shared__ __half smh[];
    __half* sK  = smh;                      // [3][64 keys][72]  (row=key, col=d)
    __half* sVt = smh + 3*CH*ASTRIDE;       // [3][64 d][72]     (row=d, col=key)

    const int tid  = threadIdx.x;
    const int warp = tid >> 5, lane = tid & 31;
    const int g = lane >> 2, tig = lane & 3;
    const int qt = blockIdx.x, bh = blockIdx.y;

    const __half* qg  = g_q  + ((size_t)bh*SEQ + qt*128)*DK;  // pre-scaled by log2e/8
    const __half* kg0 = g_k  + (size_t)bh*SEQ*DK;
    const __half* vg0 = g_vt + (size_t)bh*DK*SEQ;

    auto load_kv = [&](int buf, int kt){
        const __half* kg = kg0 + (size_t)kt*CH*DK;   // 64 keys x 64 d
        const __half* vg = vg0 + kt*CH;              // 64 d rows x 64 keys (stride SEQ)
        __half* kb = sK  + buf*(CH*ASTRIDE);
        __half* vb = sVt + buf*(DK*ASTRIDE);
#pragma unroll
        for (int i = 0; i < 4; ++i){
            int v = i*128 + tid;
            int r = v >> 3, c = (v & 7) << 3;
            cp16(saddr(kb + r*ASTRIDE + c), kg + (size_t)r*DK + c);
            cp16(saddr(vb + r*ASTRIDE + c), vg + (size_t)r*SEQ + c);
        }
        cpcommit();
    };

    load_kv(0, 0);
    load_kv(1, 1);

    // Q fragments from gmem (one-time, overlaps KV loads). 32 regs.
    uint32_t qa[2][4][4];
    {
        const int r0 = warp*32 + g;
#pragma unroll
        for (int mt = 0; mt < 2; ++mt)
#pragma unroll
        for (int kk = 0; kk < 4; ++kk){
            int r = r0 + mt*16;
            int c = kk*16 + 2*tig;
            qa[mt][kk][0] = ldu32(qg + (size_t)r*DK + c);
            qa[mt][kk][1] = ldu32(qg + (size_t)(r+8)*DK + c);
            qa[mt][kk][2] = ldu32(qg + (size_t)r*DK + c + 8);
            qa[mt][kk][3] = ldu32(qg + (size_t)(r+8)*DK + c + 8);
        }
    }

    float o[2][8][4];
#pragma unroll
    for (int i=0;i<2;i++)
#pragma unroll
        for (int j=0;j<8;j++)
#pragma unroll
            for (int e=0;e<4;e++) o[i][j][e] = 0.f;
    float rm[2][2] = {{-1e30f,-1e30f},{-1e30f,-1e30f}};
    float rl[2][2] = {{0.f,0.f},{0.f,0.f}};

    const unsigned FULL = 0xffffffffu;

    for (int kt = 0; kt < NCH; ++kt){
        if (kt == NCH-1) cpwait<0>(); else cpwait<1>();
        __syncthreads();                      // chunk kt visible; buf (kt+2)%3 free
        if (kt < NCH-2) load_kv((kt+2)%3, kt+2);

        const __half* kb = sK  + (kt%3)*(CH*ASTRIDE);
        const __half* vb = sVt + (kt%3)*(DK*ASTRIDE);

        // S[32 x 64] = q @ K^T
        float s[2][8][4];
#pragma unroll
        for (int i=0;i<2;i++)
#pragma unroll
            for (int j=0;j<8;j++)
#pragma unroll
                for (int e=0;e<4;e++) s[i][j][e] = 0.f;
#pragma unroll
        for (int kk = 0; kk < 4; ++kk){       // d-dim in k16 slices
#pragma unroll
            for (int nt = 0; nt < 8; ++nt){
                int n = nt*8 + g;             // key row
                int c = kk*16 + 2*tig;        // d col
                uint32_t b0 = ldu32(kb + n*ASTRIDE + c);
                uint32_t b1 = ldu32(kb + n*ASTRIDE + c + 8);
                mma16(s[0][nt], qa[0][kk][0],qa[0][kk][1],qa[0][kk][2],qa[0][kk][3], b0,b1);
                mma16(s[1][nt], qa[1][kk][0],qa[1][kk][1],qa[1][kk][2],qa[1][kk][3], b0,b1);
            }
        }

        // online softmax in log2 domain (rows private to warp); P left fp32 in s
#pragma unroll
        for (int mt = 0; mt < 2; ++mt){
            float m0 = -1e30f, m1 = -1e30f;
#pragma unroll
            for (int nt = 0; nt < 8; ++nt){
                m0 = fmaxf(m0, fmaxf(s[mt][nt][0], s[mt][nt][1]));
                m1 = fmaxf(m1, fmaxf(s[mt][nt][2], s[mt][nt][3]));
            }
            m0 = fmaxf(m0, __shfl_xor_sync(FULL, m0, 1));
            m0 = fmaxf(m0, __shfl_xor_sync(FULL, m0, 2));
            m1 = fmaxf(m1, __shfl_xor_sync(FULL, m1, 1));
            m1 = fmaxf(m1, __shfl_xor_sync(FULL, m1, 2));
            float nm0 = fmaxf(rm[mt][0], m0), nm1 = fmaxf(rm[mt][1], m1);
            float cor0 = exp2f(rm[mt][0] - nm0), cor1 = exp2f(rm[mt][1] - nm1);
            rm[mt][0] = nm0; rm[mt][1] = nm1;

            float l0 = 0.f, l1 = 0.f;
#pragma unroll
            for (int nt = 0; nt < 8; ++nt){
                float p0 = exp2f(s[mt][nt][0] - nm0);
                float p1 = exp2f(s[mt][nt][1] - nm0);
                float p2 = exp2f(s[mt][nt][2] - nm1);
                float p3 = exp2f(s[mt][nt][3] - nm1);
                s[mt][nt][0] = p0; s[mt][nt][1] = p1;
                s[mt][nt][2] = p2; s[mt][nt][3] = p3;
                l0 += p0 + p1; l1 += p2 + p3;
            }
            l0 += __shfl_xor_sync(FULL, l0, 1);
            l0 += __shfl_xor_sync(FULL, l0, 2);
            l1 += __shfl_xor_sync(FULL, l1, 1);
            l1 += __shfl_xor_sync(FULL, l1, 2);
            rl[mt][0] = rl[mt][0]*cor0 + l0;
            rl[mt][1] = rl[mt][1]*cor1 + l1;
#pragma unroll
            for (int nt = 0; nt < 8; ++nt){
                o[mt][nt][0] *= cor0; o[mt][nt][1] *= cor0;
                o[mt][nt][2] *= cor1; o[mt][nt][3] *= cor1;
            }
        }

        // O += P @ V : P A-fragments are direct f32x2->f16x2 packs of s (no shuffle!)
#pragma unroll
        for (int kk = 0; kk < 4; ++kk){       // key-dim in k16 slices
            uint32_t aP[2][4];
#pragma unroll
            for (int mt = 0; mt < 2; ++mt){
                aP[mt][0] = packh2(s[mt][2*kk  ][0], s[mt][2*kk  ][1]);
                aP[mt][1] = packh2(s[mt][2*kk  ][2], s[mt][2*kk  ][3]);
                aP[mt][2] = packh2(s[mt][2*kk+1][0], s[mt][2*kk+1][1]);
                aP[mt][3] = packh2(s[mt][2*kk+1][2], s[mt][2*kk+1][3]);
            }
#pragma unroll
            for (int nt = 0; nt < 8; ++nt){
                int n = nt*8 + g;             // d row of Vt
                int c = kk*16 + 2*tig;        // key col
                uint32_t b0 = ldu32(vb + n*ASTRIDE + c);
                uint32_t b1 = ldu32(vb + n*ASTRIDE + c + 8);
                mma16(o[0][nt], aP[0][0],aP[0][1],aP[0][2],aP[0][3], b0,b1);
                mma16(o[1][nt], aP[1][0],aP[1][1],aP[1][2],aP[1][3], b0,b1);
            }
        }
    }

    // normalize + write context [B,S,D] fp16
    int b = bh >> 4, h = bh & 15;
#pragma unroll
    for (int mt = 0; mt < 2; ++mt){
        float il0 = 1.f/rl[mt][0], il1 = 1.f/rl[mt][1];
        int r0 = b*SEQ + qt*128 + warp*32 + mt*16 + g;
#pragma unroll
        for (int nt = 0; nt < 8; ++nt){
            int col = h*64 + nt*8 + 2*tig;
            *(__half2*)(g_ctx + (size_t)r0*DMODEL + col) =
                __floats2half2_rn(o[mt][nt][0]*il0, o[mt][nt][1]*il0);
            *(__half2*)(g_ctx + (size_t)(r0+8)*DMODEL + col) =
                __floats2half2_rn(o[mt][nt][2]*il1, o[mt][nt][3]*il1);
        }
    }
}

// ---------------- launch ----------------
extern "C" void kernel_launch(void* const* d_in, const int* in_sizes, int n_in,
                              void* d_out, int out_size)
{
    const float* Xq = (const float*)d_in[0];
    const float* Xk = (const float*)d_in[1];
    const float* Xv = (const float*)d_in[2];
    const float* Wq = (const float*)d_in[3]; const float* bq = (const float*)d_in[4];
    const float* Wk = (const float*)d_in[5]; const float* bk = (const float*)d_in[6];
    const float* Wv = (const float*)d_in[7]; const float* bv = (const float*)d_in[8];
    const float* Wo = (const float*)d_in[9]; const float* bo = (const float*)d_in[10];
    float* out = (float*)d_out;

    void *gq, *gk, *gvt, *gctx, *gxq, *gxk, *gxv, *gwq, *gwk, *gwv, *gwo;
    cudaGetSymbolAddress(&gq,  g_q);
    cudaGetSymbolAddress(&gk,  g_k);
    cudaGetSymbolAddress(&gvt, g_vt);
    cudaGetSymbolAddress(&gctx, g_ctx);
    cudaGetSymbolAddress(&gxq, g_xq);
    cudaGetSymbolAddress(&gxk, g_xk);
    cudaGetSymbolAddress(&gxv, g_xv);
    cudaGetSymbolAddress(&gwq, g_wq);
    cudaGetSymbolAddress(&gwk, g_wk);
    cudaGetSymbolAddress(&gwv, g_wv);
    cudaGetSymbolAddress(&gwo, g_wo);

    cudaFuncSetAttribute(gemm_fp16,  cudaFuncAttributeMaxDynamicSharedMemorySize, GEMM_SMEM_BYTES);
    cudaFuncSetAttribute(attn_kernel, cudaFuncAttributeMaxDynamicSharedMemorySize, ATTN_SMEM_BYTES);

    // convert raw inputs + weights to fp16 once
    {
        int n4x = (MROWS*DMODEL)/4;
        dim3 gx((n4x + 255)/256, 3);
        cvt3_kernel<<<gx, 256>>>((const float4*)Xq, (const float4*)Xk, (const float4*)Xv,
                                 (__half2*)gxq, (__half2*)gxk, (__half2*)gxv, n4x);
        int n4w = (DMODEL*DMODEL)/4;
        dim3 gw((n4w + 255)/256, 4);
        cvt4_kernel<<<gw, 256>>>((const float4*)Wq, (const float4*)Wk,
                                 (const float4*)Wv, (const float4*)Wo,
                                 (__half2*)gwq, (__half2*)gwk, (__half2*)gwv, (__half2*)gwo, n4w);
    }

    const float qscale = 0.125f * 1.4426950408889634f;   // 1/sqrt(dk) * log2(e)
    GemmArgs aq{(const __half*)gxq, (const __half*)gwq, bq, gq,   qscale, 1};
    GemmArgs ak{(const __half*)gxk, (const __half*)gwk, bk, gk,   1.0f,   1};
    GemmArgs av{(const __half*)gxv, (const __half*)gwv, bv, gvt,  1.0f,   2};
    GemmArgs ao{(const __half*)gctx,(const __half*)gwo, bo, (void*)out, 1.0f, 0};

    // merged QKV: one launch, grid.z selects projection
    dim3 gqkv(DMODEL/128, MROWS/256, 3);
    gemm_fp16<<<gqkv, 256, GEMM_SMEM_BYTES>>>(aq, ak, av);

    attn_kernel<<<dim3(SEQ/128, BATCH*NHEAD), 128, ATTN_SMEM_BYTES>>>();

    dim3 go(DMODEL/128, MROWS/256, 1);
    gemm_fp16<<<go, 256, GEMM_SMEM_BYTES>>>(ao, ao, ao);
}

// round 6
// speedup vs baseline: 2.0888x; 1.0350x over previous
#include <cuda_runtime.h>
#include <cuda_fp16.h>
#include <cstdint>

#define SEQ    2048
#define BATCH  4
#define NHEAD  16
#define DK     64
#define DMODEL 1024
#define MROWS  (BATCH*SEQ)

// Scratch (allocation-free rule: device globals). All fp16.
__device__ __half g_q[BATCH*NHEAD*SEQ*DK];     // [b,h,s,d], pre-scaled by log2e/8
__device__ __half g_k[BATCH*NHEAD*SEQ*DK];     // [b,h,s,d]
__device__ __half g_v[BATCH*NHEAD*SEQ*DK];     // [b,h,s,d]
__device__ __half g_ctx[(size_t)MROWS*DMODEL]; // [b*s, d_model]
// fp16 copies of raw inputs / weights
__device__ __half g_xq[(size_t)MROWS*DMODEL];
__device__ __half g_xk[(size_t)MROWS*DMODEL];
__device__ __half g_xv[(size_t)MROWS*DMODEL];
__device__ __half g_wq[DMODEL*DMODEL];
__device__ __half g_wk[DMODEL*DMODEL];
__device__ __half g_wv[DMODEL*DMODEL];
__device__ __half g_wo[DMODEL*DMODEL];

// ---------------- helpers ----------------
__device__ __forceinline__ uint32_t saddr(const void* p){
    return (uint32_t)__cvta_generic_to_shared(p);
}
__device__ __forceinline__ void cp16(uint32_t s, const void* g){
    asm volatile("cp.async.cg.shared.global [%0], [%1], 16;\n" :: "r"(s), "l"(g));
}
__device__ __forceinline__ void cpcommit(){ asm volatile("cp.async.commit_group;\n"); }
template<int N> __device__ __forceinline__ void cpwait(){
    asm volatile("cp.async.wait_group %0;\n" :: "n"(N));
}
__device__ __forceinline__ void mma16(float c[4],
        uint32_t a0,uint32_t a1,uint32_t a2,uint32_t a3,
        uint32_t b0,uint32_t b1){
    asm volatile(
      "mma.sync.aligned.m16n8k16.row.col.f32.f16.f16.f32 "
      "{%0,%1,%2,%3},{%4,%5,%6,%7},{%8,%9},{%0,%1,%2,%3};\n"
      : "+f"(c[0]), "+f"(c[1]), "+f"(c[2]), "+f"(c[3])
      : "r"(a0), "r"(a1), "r"(a2), "r"(a3), "r"(b0), "r"(b1));
}
__device__ __forceinline__ void ldsm4(uint32_t& r0,uint32_t& r1,uint32_t& r2,uint32_t& r3,uint32_t a){
    asm volatile("ldmatrix.sync.aligned.m8n8.x4.shared.b16 {%0,%1,%2,%3}, [%4];"
      : "=r"(r0),"=r"(r1),"=r"(r2),"=r"(r3) : "r"(a));
}
__device__ __forceinline__ void ldsm4t(uint32_t& r0,uint32_t& r1,uint32_t& r2,uint32_t& r3,uint32_t a){
    asm volatile("ldmatrix.sync.aligned.m8n8.x4.trans.shared.b16 {%0,%1,%2,%3}, [%4];"
      : "=r"(r0),"=r"(r1),"=r"(r2),"=r"(r3) : "r"(a));
}
__device__ __forceinline__ uint32_t packh2(float lo, float hi){
    __half2 h = __floats2half2_rn(lo, hi);
    return *reinterpret_cast<uint32_t*>(&h);
}
__device__ __forceinline__ uint32_t ldu32(const __half* p){
    return *reinterpret_cast<const uint32_t*>(p);
}

// ---------------- convert kernels (fp32 -> fp16 RN) ----------------
__global__ void cvt3_kernel(const float4* __restrict__ a, const float4* __restrict__ b,
                            const float4* __restrict__ c, __half2* __restrict__ oa,
                            __half2* __restrict__ ob, __half2* __restrict__ oc, int n4)
{
    int i = blockIdx.x*blockDim.x + threadIdx.x;
    if (i >= n4) return;
    const float4* s = (blockIdx.y==0) ? a : (blockIdx.y==1) ? b : c;
    __half2* d      = (blockIdx.y==0) ? oa : (blockIdx.y==1) ? ob : oc;
    float4 v = s[i];
    d[2*i]   = __floats2half2_rn(v.x, v.y);
    d[2*i+1] = __floats2half2_rn(v.z, v.w);
}
__global__ void cvt4_kernel(const float4* __restrict__ a, const float4* __restrict__ b,
                            const float4* __restrict__ c, const float4* __restrict__ e,
                            __half2* __restrict__ oa, __half2* __restrict__ ob,
                            __half2* __restrict__ oc, __half2* __restrict__ oe, int n4)
{
    int i = blockIdx.x*blockDim.x + threadIdx.x;
    if (i >= n4) return;
    const float4* s = (blockIdx.y==0) ? a : (blockIdx.y==1) ? b : (blockIdx.y==2) ? c : e;
    __half2* d      = (blockIdx.y==0) ? oa : (blockIdx.y==1) ? ob : (blockIdx.y==2) ? oc : oe;
    float4 v = s[i];
    d[2*i]   = __floats2half2_rn(v.x, v.y);
    d[2*i+1] = __floats2half2_rn(v.z, v.w);
}

// ---------------- GEMM fp16: C[M,N] = X[M,K] @ W[N,K]^T + bias ----------------
// Block tile 256x128x64, 256 threads (8 warps as 4m x 2n), warp tile 64x64.
// 3-stage cp.async pipeline; fragments via ldmatrix.x4 (8 LDSM + 32 MMA per ks).
// mode 0: dst fp32 [m,1024]            (output projection)
// mode 1: dst fp16 [b,h,s,64], scaled  (q, k, v)
struct GemmArgs { const __half* A; const __half* W; const float* bias;
                  void* dst; float scale; int mode; };

#define KT       64
#define GSTRIDE  72     // halves per smem row (64 + 8 pad) = 144B, LDSM conflict-free
#define GEMM_SMEM_BYTES (3*(256+128)*GSTRIDE*2)

__global__ void __launch_bounds__(256,1) gemm_fp16(GemmArgs ga0, GemmArgs ga1, GemmArgs ga2)
{
    extern __shared__ __half smh[];
    __half* sA = smh;                       // [3][256][72]
    __half* sB = smh + 3*256*GSTRIDE;       // [3][128][72]
    const int tid = threadIdx.x;
    const int m0 = blockIdx.y << 8, n0 = blockIdx.x << 7;

    GemmArgs ga = (blockIdx.z==0) ? ga0 : (blockIdx.z==1) ? ga1 : ga2;
    const __half* __restrict__ A = ga.A;
    const __half* __restrict__ W = ga.W;

    auto load_tile = [&](int buf, int kt){
        const __half* Ag = A + (size_t)m0*DMODEL + kt*KT;
        const __half* Wg = W + (size_t)n0*DMODEL + kt*KT;
        __half* a = sA + buf*(256*GSTRIDE);
        __half* b = sB + buf*(128*GSTRIDE);
#pragma unroll
        for (int i = 0; i < 8; ++i){
            int v = i*256 + tid;
            int r = v >> 3, c = (v & 7) << 3;
            cp16(saddr(a + r*GSTRIDE + c), Ag + (size_t)r*DMODEL + c);
        }
#pragma unroll
        for (int i = 0; i < 4; ++i){
            int v = i*256 + tid;
            int r = v >> 3, c = (v & 7) << 3;
            cp16(saddr(b + r*GSTRIDE + c), Wg + (size_t)r*DMODEL + c);
        }
        cpcommit();
    };

    float acc[4][8][4];
#pragma unroll
    for (int i=0;i<4;i++)
#pragma unroll
        for (int j=0;j<8;j++)
#pragma unroll
            for (int e=0;e<4;e++) acc[i][j][e] = 0.f;

    load_tile(0, 0);
    load_tile(1, 1);

    const int warp = tid >> 5, lane = tid & 31;
    const int wm = warp >> 1, wn = warp & 1;
    const int g = lane >> 2, tig = lane & 3;
    // LDSM lane->address patterns
    const int lrow16 = lane & 15;                     // A-style row
    const int lcol8  = (lane >> 4) << 3;              // A-style col select (0/8)
    const int brow   = (lane & 7) + lcol8;            // B-style row
    const int bcol8  = ((lane >> 3) & 1) << 3;        // B-style col select (0/8)

    const uint32_t sAa = saddr(sA), sBa = saddr(sB);

    for (int kt = 0; kt < 16; ++kt){
        if (kt == 15) cpwait<0>(); else cpwait<1>();
        __syncthreads();
        if (kt < 14) load_tile((kt+2)%3, kt+2);

        const uint32_t abuf = sAa + (kt%3)*(256*GSTRIDE*2);
        const uint32_t bbuf = sBa + (kt%3)*(128*GSTRIDE*2);
#pragma unroll
        for (int ks = 0; ks < 4; ++ks){      // 4 x k16
            uint32_t af[4][4];
#pragma unroll
            for (int mt = 0; mt < 4; ++mt){
                uint32_t a = abuf + (((wm*64 + mt*16 + lrow16)*GSTRIDE + ks*16 + lcol8) << 1);
                ldsm4(af[mt][0], af[mt][1], af[mt][2], af[mt][3], a);
            }
#pragma unroll
            for (int ntp = 0; ntp < 4; ++ntp){
                uint32_t b0,b1,b2,b3;
                uint32_t b = bbuf + (((wn*64 + ntp*16 + brow)*GSTRIDE + ks*16 + bcol8) << 1);
                ldsm4(b0,b1,b2,b3, b);
#pragma unroll
                for (int mt = 0; mt < 4; ++mt){
                    mma16(acc[mt][2*ntp  ], af[mt][0],af[mt][1],af[mt][2],af[mt][3], b0,b1);
                    mma16(acc[mt][2*ntp+1], af[mt][0],af[mt][1],af[mt][2],af[mt][3], b2,b3);
                }
            }
        }
    }

    // epilogue
    const float* bias = ga.bias;
    const float scale = ga.scale;
    const int mode = ga.mode;
#pragma unroll
    for (int mt = 0; mt < 4; ++mt){
#pragma unroll
        for (int nt = 0; nt < 8; ++nt){
            int row = m0 + wm*64 + mt*16 + g;
            int col = n0 + wn*64 + nt*8 + 2*tig;
#pragma unroll
            for (int half = 0; half < 2; ++half){
                int r = row + half*8;
                float v0 = (acc[mt][nt][2*half+0] + bias[col])   * scale;
                float v1 = (acc[mt][nt][2*half+1] + bias[col+1]) * scale;
                if (mode == 0){
                    *(float2*)((float*)ga.dst + (size_t)r*DMODEL + col) = make_float2(v0, v1);
                } else {
                    int bb = r >> 11, s = r & 2047, h = col >> 6, d = col & 63;
                    *(__half2*)((__half*)ga.dst + (((size_t)(bb*NHEAD + h))*SEQ + s)*DK + d) =
                        __floats2half2_rn(v0, v1);
                }
            }
        }
    }
}

// ---------------- Flash attention fp16 + LDSM ----------------
// 128-thread CTAs (4 warps x 32 Q rows), 2 CTAs/SM.
// K fragments via ldmatrix.x4; V in natural [s,d], PV fragments via ldmatrix.x4.trans.
// S accumulators pack directly into P A-fragments. 3-stage cp.async, 1 barrier/chunk.
#define CH   64
#define NCH  (SEQ/CH)   // 32
#define ASTRIDE 72      // halves per smem row
#define ATTN_SMEM_BYTES (2*2*(3*CH*ASTRIDE))   // K + V, 55,296 B

__global__ void __launch_bounds__(128,2) attn_kernel()
{
    extern __shared__ __half smh[];
    __half* sK = smh;                      // [3][64 keys][72]
    __half* sV = smh + 3*CH*ASTRIDE;       // [3][64 keys][72]

    const int tid  = threadIdx.x;
    const int warp = tid >> 5, lane = tid & 31;
    const int g = lane >> 2, tig = lane & 3;
    const int qt = blockIdx.x, bh = blockIdx.y;

    const __half* qg  = g_q + ((size_t)bh*SEQ + qt*128)*DK;  // pre-scaled by log2e/8
    const __half* kg0 = g_k + (size_t)bh*SEQ*DK;
    const __half* vg0 = g_v + (size_t)bh*SEQ*DK;

    auto load_kv = [&](int buf, int kt){
        const __half* kg = kg0 + (size_t)kt*CH*DK;
        const __half* vg = vg0 + (size_t)kt*CH*DK;
        __half* kb = sK + buf*(CH*ASTRIDE);
        __half* vb = sV + buf*(CH*ASTRIDE);
#pragma unroll
        for (int i = 0; i < 4; ++i){
            int v = i*128 + tid;
            int r = v >> 3, c = (v & 7) << 3;
            cp16(saddr(kb + r*ASTRIDE + c), kg + (size_t)r*DK + c);
            cp16(saddr(vb + r*ASTRIDE + c), vg + (size_t)r*DK + c);
        }
        cpcommit();
    };

    load_kv(0, 0);
    load_kv(1, 1);

    // Q fragments from gmem (one-time, overlaps KV loads). 32 regs.
    uint32_t qa[2][4][4];
    {
        const int r0 = warp*32 + g;
#pragma unroll
        for (int mt = 0; mt < 2; ++mt)
#pragma unroll
        for (int kk = 0; kk < 4; ++kk){
            int r = r0 + mt*16;
            int c = kk*16 + 2*tig;
            qa[mt][kk][0] = ldu32(qg + (size_t)r*DK + c);
            qa[mt][kk][1] = ldu32(qg + (size_t)(r+8)*DK + c);
            qa[mt][kk][2] = ldu32(qg + (size_t)r*DK + c + 8);
            qa[mt][kk][3] = ldu32(qg + (size_t)(r+8)*DK + c + 8);
        }
    }

    float o[2][8][4];
#pragma unroll
    for (int i=0;i<2;i++)
#pragma unroll
        for (int j=0;j<8;j++)
#pragma unroll
            for (int e=0;e<4;e++) o[i][j][e] = 0.f;
    float rm[2][2] = {{-1e30f,-1e30f},{-1e30f,-1e30f}};
    float rl[2][2] = {{0.f,0.f},{0.f,0.f}};

    const unsigned FULL = 0xffffffffu;
    const int lrow16 = lane & 15;
    const int lcol8  = (lane >> 4) << 3;
    const int brow   = (lane & 7) + lcol8;
    const int bcol8  = ((lane >> 3) & 1) << 3;
    const uint32_t sKa = saddr(sK), sVa = saddr(sV);

    for (int kt = 0; kt < NCH; ++kt){
        if (kt == NCH-1) cpwait<0>(); else cpwait<1>();
        __syncthreads();                      // chunk kt visible; buf (kt+2)%3 free
        if (kt < NCH-2) load_kv((kt+2)%3, kt+2);

        const uint32_t kbuf = sKa + (kt%3)*(CH*ASTRIDE*2);
        const uint32_t vbuf = sVa + (kt%3)*(CH*ASTRIDE*2);

        // S[32 x 64] = q @ K^T : per kk, 4 LDSM.x4 + 16 MMA
        float s[2][8][4];
#pragma unroll
        for (int i=0;i<2;i++)
#pragma unroll
            for (int j=0;j<8;j++)
#pragma unroll
                for (int e=0;e<4;e++) s[i][j][e] = 0.f;
#pragma unroll
        for (int kk = 0; kk < 4; ++kk){       // d-dim k16 slices
#pragma unroll
            for (int ntp = 0; ntp < 4; ++ntp){ // key n16 tiles
                uint32_t b0,b1,b2,b3;
                uint32_t a = kbuf + (((ntp*16 + brow)*ASTRIDE + kk*16 + bcol8) << 1);
                ldsm4(b0,b1,b2,b3, a);
                mma16(s[0][2*ntp  ], qa[0][kk][0],qa[0][kk][1],qa[0][kk][2],qa[0][kk][3], b0,b1);
                mma16(s[1][2*ntp  ], qa[1][kk][0],qa[1][kk][1],qa[1][kk][2],qa[1][kk][3], b0,b1);
                mma16(s[0][2*ntp+1], qa[0][kk][0],qa[0][kk][1],qa[0][kk][2],qa[0][kk][3], b2,b3);
                mma16(s[1][2*ntp+1], qa[1][kk][0],qa[1][kk][1],qa[1][kk][2],qa[1][kk][3], b2,b3);
            }
        }

        // online softmax in log2 domain (rows private to warp)
#pragma unroll
        for (int mt = 0; mt < 2; ++mt){
            float m0 = -1e30f, m1 = -1e30f;
#pragma unroll
            for (int nt = 0; nt < 8; ++nt){
                m0 = fmaxf(m0, fmaxf(s[mt][nt][0], s[mt][nt][1]));
                m1 = fmaxf(m1, fmaxf(s[mt][nt][2], s[mt][nt][3]));
            }
            m0 = fmaxf(m0, __shfl_xor_sync(FULL, m0, 1));
            m0 = fmaxf(m0, __shfl_xor_sync(FULL, m0, 2));
            m1 = fmaxf(m1, __shfl_xor_sync(FULL, m1, 1));
            m1 = fmaxf(m1, __shfl_xor_sync(FULL, m1, 2));
            float nm0 = fmaxf(rm[mt][0], m0), nm1 = fmaxf(rm[mt][1], m1);
            bool upd = (nm0 != rm[mt][0]) || (nm1 != rm[mt][1]);

            float l0 = 0.f, l1 = 0.f;
#pragma unroll
            for (int nt = 0; nt < 8; ++nt){
                float p0 = exp2f(s[mt][nt][0] - nm0);
                float p1 = exp2f(s[mt][nt][1] - nm0);
                float p2 = exp2f(s[mt][nt][2] - nm1);
                float p3 = exp2f(s[mt][nt][3] - nm1);
                s[mt][nt][0] = p0; s[mt][nt][1] = p1;
                s[mt][nt][2] = p2; s[mt][nt][3] = p3;
                l0 += p0 + p1; l1 += p2 + p3;
            }
            l0 += __shfl_xor_sync(FULL, l0, 1);
            l0 += __shfl_xor_sync(FULL, l0, 2);
            l1 += __shfl_xor_sync(FULL, l1, 1);
            l1 += __shfl_xor_sync(FULL, l1, 2);

            if (__any_sync(FULL, upd)){       // warp-uniform; exact (exp2(0)==1)
                float cor0 = exp2f(rm[mt][0] - nm0);
                float cor1 = exp2f(rm[mt][1] - nm1);
                rm[mt][0] = nm0; rm[mt][1] = nm1;
                rl[mt][0] = rl[mt][0]*cor0 + l0;
                rl[mt][1] = rl[mt][1]*cor1 + l1;
#pragma unroll
                for (int nt = 0; nt < 8; ++nt){
                    o[mt][nt][0] *= cor0; o[mt][nt][1] *= cor0;
                    o[mt][nt][2] *= cor1; o[mt][nt][3] *= cor1;
                }
            } else {
                rl[mt][0] += l0;
                rl[mt][1] += l1;
            }
        }

        // O += P @ V : P A-frags = direct packs; V B-frags via LDSM.trans
#pragma unroll
        for (int kk = 0; kk < 4; ++kk){       // key-dim k16 slices
            uint32_t aP[2][4];
#pragma unroll
            for (int mt = 0; mt < 2; ++mt){
                aP[mt][0] = packh2(s[mt][2*kk  ][0], s[mt][2*kk  ][1]);
                aP[mt][1] = packh2(s[mt][2*kk  ][2], s[mt][2*kk  ][3]);
                aP[mt][2] = packh2(s[mt][2*kk+1][0], s[mt][2*kk+1][1]);
                aP[mt][3] = packh2(s[mt][2*kk+1][2], s[mt][2*kk+1][3]);
            }
#pragma unroll
            for (int dp = 0; dp < 4; ++dp){   // d n16 tiles
                uint32_t b0,b1,b2,b3;
                uint32_t a = vbuf + (((kk*16 + lrow16)*ASTRIDE + dp*16 + lcol8) << 1);
                ldsm4t(b0,b1,b2,b3, a);
                mma16(o[0][2*dp  ], aP[0][0],aP[0][1],aP[0][2],aP[0][3], b0,b1);
                mma16(o[1][2*dp  ], aP[1][0],aP[1][1],aP[1][2],aP[1][3], b0,b1);
                mma16(o[0][2*dp+1], aP[0][0],aP[0][1],aP[0][2],aP[0][3], b2,b3);
                mma16(o[1][2*dp+1], aP[1][0],aP[1][1],aP[1][2],aP[1][3], b2,b3);
            }
        }
    }

    // normalize + write context [B,S,D] fp16
    int b = bh >> 4, h = bh & 15;
#pragma unroll
    for (int mt = 0; mt < 2; ++mt){
        float il0 = 1.f/rl[mt][0], il1 = 1.f/rl[mt][1];
        int r0 = b*SEQ + qt*128 + warp*32 + mt*16 + g;
#pragma unroll
        for (int nt = 0; nt < 8; ++nt){
            int col = h*64 + nt*8 + 2*tig;
            *(__half2*)(g_ctx + (size_t)r0*DMODEL + col) =
                __floats2half2_rn(o[mt][nt][0]*il0, o[mt][nt][1]*il0);
            *(__half2*)(g_ctx + (size_t)(r0+8)*DMODEL + col) =
                __floats2half2_rn(o[mt][nt][2]*il1, o[mt][nt][3]*il1);
        }
    }
}

// ---------------- launch ----------------
extern "C" void kernel_launch(void* const* d_in, const int* in_sizes, int n_in,
                              void* d_out, int out_size)
{
    const float* Xq = (const float*)d_in[0];
    const float* Xk = (const float*)d_in[1];
    const float* Xv = (const float*)d_in[2];
    const float* Wq = (const float*)d_in[3]; const float* bq = (const float*)d_in[4];
    const float* Wk = (const float*)d_in[5]; const float* bk = (const float*)d_in[6];
    const float* Wv = (const float*)d_in[7]; const float* bv = (const float*)d_in[8];
    const float* Wo = (const float*)d_in[9]; const float* bo = (const float*)d_in[10];
    float* out = (float*)d_out;

    void *gq, *gk, *gv, *gctx, *gxq, *gxk, *gxv, *gwq, *gwk, *gwv, *gwo;
    cudaGetSymbolAddress(&gq,  g_q);
    cudaGetSymbolAddress(&gk,  g_k);
    cudaGetSymbolAddress(&gv,  g_v);
    cudaGetSymbolAddress(&gctx, g_ctx);
    cudaGetSymbolAddress(&gxq, g_xq);
    cudaGetSymbolAddress(&gxk, g_xk);
    cudaGetSymbolAddress(&gxv, g_xv);
    cudaGetSymbolAddress(&gwq, g_wq);
    cudaGetSymbolAddress(&gwk, g_wk);
    cudaGetSymbolAddress(&gwv, g_wv);
    cudaGetSymbolAddress(&gwo, g_wo);

    cudaFuncSetAttribute(gemm_fp16,  cudaFuncAttributeMaxDynamicSharedMemorySize, GEMM_SMEM_BYTES);
    cudaFuncSetAttribute(attn_kernel, cudaFuncAttributeMaxDynamicSharedMemorySize, ATTN_SMEM_BYTES);

    // convert raw inputs + weights to fp16 once
    {
        int n4x = (MROWS*DMODEL)/4;
        dim3 gx((n4x + 255)/256, 3);
        cvt3_kernel<<<gx, 256>>>((const float4*)Xq, (const float4*)Xk, (const float4*)Xv,
                                 (__half2*)gxq, (__half2*)gxk, (__half2*)gxv, n4x);
        int n4w = (DMODEL*DMODEL)/4;
        dim3 gw((n4w + 255)/256, 4);
        cvt4_kernel<<<gw, 256>>>((const float4*)Wq, (const float4*)Wk,
                                 (const float4*)Wv, (const float4*)Wo,
                                 (__half2*)gwq, (__half2*)gwk, (__half2*)gwv, (__half2*)gwo, n4w);
    }

    const float qscale = 0.125f * 1.4426950408889634f;   // 1/sqrt(dk) * log2(e)
    GemmArgs aq{(const __half*)gxq, (const __half*)gwq, bq, gq,   qscale, 1};
    GemmArgs ak{(const __half*)gxk, (const __half*)gwk, bk, gk,   1.0f,   1};
    GemmArgs av{(const __half*)gxv, (const __half*)gwv, bv, gv,   1.0f,   1};
    GemmArgs ao{(const __half*)gctx,(const __half*)gwo, bo, (void*)out, 1.0f, 0};

    // merged QKV: one launch, grid.z selects projection
    dim3 gqkv(DMODEL/128, MROWS/256, 3);
    gemm_fp16<<<gqkv, 256, GEMM_SMEM_BYTES>>>(aq, ak, av);

    attn_kernel<<<dim3(SEQ/128, BATCH*NHEAD), 128, ATTN_SMEM_BYTES>>>();

    dim3 go(DMODEL/128, MROWS/256, 1);
    gemm_fp16<<<go, 256, GEMM_SMEM_BYTES>>>(ao, ao, ao);
}

// round 8
// speedup vs baseline: 2.1614x; 1.0348x over previous
#include <cuda_runtime.h>
#include <cuda_fp16.h>
#include <cstdint>

#define SEQ    2048
#define BATCH  4
#define NHEAD  16
#define DK     64
#define DMODEL 1024
#define MROWS  (BATCH*SEQ)

// Scratch (allocation-free rule: device globals). All fp16.
__device__ __half g_q[BATCH*NHEAD*SEQ*DK];     // [b,h,s,d], pre-scaled by log2e/8
__device__ __half g_k[BATCH*NHEAD*SEQ*DK];     // [b,h,s,d]
__device__ __half g_v[BATCH*NHEAD*SEQ*DK];     // [b,h,s,d]
__device__ __half g_ctx[(size_t)MROWS*DMODEL]; // [b*s, d_model]
// fp16 copies of raw inputs / weights
__device__ __half g_xq[(size_t)MROWS*DMODEL];
__device__ __half g_xk[(size_t)MROWS*DMODEL];
__device__ __half g_xv[(size_t)MROWS*DMODEL];
__device__ __half g_wq[DMODEL*DMODEL];
__device__ __half g_wk[DMODEL*DMODEL];
__device__ __half g_wv[DMODEL*DMODEL];
__device__ __half g_wo[DMODEL*DMODEL];

// ---------------- helpers ----------------
__device__ __forceinline__ uint32_t saddr(const void* p){
    return (uint32_t)__cvta_generic_to_shared(p);
}
__device__ __forceinline__ void cp16(uint32_t s, const void* g){
    asm volatile("cp.async.cg.shared.global [%0], [%1], 16;\n" :: "r"(s), "l"(g));
}
__device__ __forceinline__ void cpcommit(){ asm volatile("cp.async.commit_group;\n"); }
template<int N> __device__ __forceinline__ void cpwait(){
    asm volatile("cp.async.wait_group %0;\n" :: "n"(N));
}
__device__ __forceinline__ void mma16(float c[4],
        uint32_t a0,uint32_t a1,uint32_t a2,uint32_t a3,
        uint32_t b0,uint32_t b1){
    asm volatile(
      "mma.sync.aligned.m16n8k16.row.col.f32.f16.f16.f32 "
      "{%0,%1,%2,%3},{%4,%5,%6,%7},{%8,%9},{%0,%1,%2,%3};\n"
      : "+f"(c[0]), "+f"(c[1]), "+f"(c[2]), "+f"(c[3])
      : "r"(a0), "r"(a1), "r"(a2), "r"(a3), "r"(b0), "r"(b1));
}
__device__ __forceinline__ void ldsm4(uint32_t& r0,uint32_t& r1,uint32_t& r2,uint32_t& r3,uint32_t a){
    asm volatile("ldmatrix.sync.aligned.m8n8.x4.shared.b16 {%0,%1,%2,%3}, [%4];"
      : "=r"(r0),"=r"(r1),"=r"(r2),"=r"(r3) : "r"(a));
}
__device__ __forceinline__ void ldsm4t(uint32_t& r0,uint32_t& r1,uint32_t& r2,uint32_t& r3,uint32_t a){
    asm volatile("ldmatrix.sync.aligned.m8n8.x4.trans.shared.b16 {%0,%1,%2,%3}, [%4];"
      : "=r"(r0),"=r"(r1),"=r"(r2),"=r"(r3) : "r"(a));
}
__device__ __forceinline__ uint32_t packh2(float lo, float hi){
    __half2 h = __floats2half2_rn(lo, hi);
    return *reinterpret_cast<uint32_t*>(&h);
}
__device__ __forceinline__ uint32_t ldu32(const __half* p){
    return *reinterpret_cast<const uint32_t*>(p);
}

// ---------------- convert kernels (fp32 -> fp16 RN) ----------------
__global__ void cvt3_kernel(const float4* __restrict__ a, const float4* __restrict__ b,
                            const float4* __restrict__ c, __half2* __restrict__ oa,
                            __half2* __restrict__ ob, __half2* __restrict__ oc, int n4)
{
    int i = blockIdx.x*blockDim.x + threadIdx.x;
    if (i >= n4) return;
    const float4* s = (blockIdx.y==0) ? a : (blockIdx.y==1) ? b : c;
    __half2* d      = (blockIdx.y==0) ? oa : (blockIdx.y==1) ? ob : oc;
    float4 v = s[i];
    d[2*i]   = __floats2half2_rn(v.x, v.y);
    d[2*i+1] = __floats2half2_rn(v.z, v.w);
}
__global__ void cvt4_kernel(const float4* __restrict__ a, const float4* __restrict__ b,
                            const float4* __restrict__ c, const float4* __restrict__ e,
                            __half2* __restrict__ oa, __half2* __restrict__ ob,
                            __half2* __restrict__ oc, __half2* __restrict__ oe, int n4)
{
    int i = blockIdx.x*blockDim.x + threadIdx.x;
    if (i >= n4) return;
    const float4* s = (blockIdx.y==0) ? a : (blockIdx.y==1) ? b : (blockIdx.y==2) ? c : e;
    __half2* d      = (blockIdx.y==0) ? oa : (blockIdx.y==1) ? ob : (blockIdx.y==2) ? oc : oe;
    float4 v = s[i];
    d[2*i]   = __floats2half2_rn(v.x, v.y);
    d[2*i+1] = __floats2half2_rn(v.z, v.w);
}

// ---------------- GEMM fp16: C[M,N] = X[M,K] @ W[N,K]^T + bias ----------------
// 128-thread CTAs, block tile 128x128x64, 4 warps (2m x 2n), warp tile 64x64.
// 3-stage cp.async pipeline; fragments via ldmatrix.x4. 2 CTAs/SM ->
// two independent barrier domains keep the HMMA pipe fed across syncs.
// mode 0: dst fp32 [m,1024]            (output projection)
// mode 1: dst fp16 [b,h,s,64], scaled  (q, k, v)
struct GemmArgs { const __half* A; const __half* W; const float* bias;
                  void* dst; float scale; int mode; };

#define KT       64
#define GSTRIDE  72     // halves per smem row (64 + 8 pad) = 144B, LDSM conflict-free
#define GEMM_SMEM_BYTES (3*(128+128)*GSTRIDE*2)   // 110,592 B -> 2 CTAs/SM

__global__ void __launch_bounds__(128,2) gemm_fp16(GemmArgs ga0, GemmArgs ga1, GemmArgs ga2)
{
    extern __shared__ __half smh[];
    __half* sA = smh;                       // [3][128][72]
    __half* sB = smh + 3*128*GSTRIDE;       // [3][128][72]
    const int tid = threadIdx.x;
    const int m0 = blockIdx.y << 7, n0 = blockIdx.x << 7;

    GemmArgs ga = (blockIdx.z==0) ? ga0 : (blockIdx.z==1) ? ga1 : ga2;
    const __half* __restrict__ A = ga.A;
    const __half* __restrict__ W = ga.W;

    auto load_tile = [&](int buf, int kt){
        const __half* Ag = A + (size_t)m0*DMODEL + kt*KT;
        const __half* Wg = W + (size_t)n0*DMODEL + kt*KT;
        __half* a = sA + buf*(128*GSTRIDE);
        __half* b = sB + buf*(128*GSTRIDE);
#pragma unroll
        for (int i = 0; i < 8; ++i){
            int v = i*128 + tid;
            int r = v >> 3, c = (v & 7) << 3;
            cp16(saddr(a + r*GSTRIDE + c), Ag + (size_t)r*DMODEL + c);
            cp16(saddr(b + r*GSTRIDE + c), Wg + (size_t)r*DMODEL + c);
        }
        cpcommit();
    };

    float acc[4][8][4];
#pragma unroll
    for (int i=0;i<4;i++)
#pragma unroll
        for (int j=0;j<8;j++)
#pragma unroll
            for (int e=0;e<4;e++) acc[i][j][e] = 0.f;

    load_tile(0, 0);
    load_tile(1, 1);

    const int warp = tid >> 5, lane = tid & 31;
    const int wm = warp >> 1, wn = warp & 1;
    const int g = lane >> 2, tig = lane & 3;
    // LDSM lane->address patterns
    const int lrow16 = lane & 15;                     // A-style row
    const int lcol8  = (lane >> 4) << 3;              // A-style col select (0/8)
    const int brow   = (lane & 7) + lcol8;            // B-style row
    const int bcol8  = ((lane >> 3) & 1) << 3;        // B-style col select (0/8)

    const uint32_t sAa = saddr(sA), sBa = saddr(sB);

    for (int kt = 0; kt < 16; ++kt){
        if (kt == 15) cpwait<0>(); else cpwait<1>();
        __syncthreads();
        if (kt < 14) load_tile((kt+2)%3, kt+2);

        const uint32_t abuf = sAa + (kt%3)*(128*GSTRIDE*2);
        const uint32_t bbuf = sBa + (kt%3)*(128*GSTRIDE*2);
#pragma unroll
        for (int ks = 0; ks < 4; ++ks){      // 4 x k16
            uint32_t af[4][4];
#pragma unroll
            for (int mt = 0; mt < 4; ++mt){
                uint32_t a = abuf + (((wm*64 + mt*16 + lrow16)*GSTRIDE + ks*16 + lcol8) << 1);
                ldsm4(af[mt][0], af[mt][1], af[mt][2], af[mt][3], a);
            }
#pragma unroll
            for (int ntp = 0; ntp < 4; ++ntp){
                uint32_t b0,b1,b2,b3;
                uint32_t b = bbuf + (((wn*64 + ntp*16 + brow)*GSTRIDE + ks*16 + bcol8) << 1);
                ldsm4(b0,b1,b2,b3, b);
#pragma unroll
                for (int mt = 0; mt < 4; ++mt){
                    mma16(acc[mt][2*ntp  ], af[mt][0],af[mt][1],af[mt][2],af[mt][3], b0,b1);
                    mma16(acc[mt][2*ntp+1], af[mt][0],af[mt][1],af[mt][2],af[mt][3], b2,b3);
                }
            }
        }
    }

    // epilogue
    const float* bias = ga.bias;
    const float scale = ga.scale;
    const int mode = ga.mode;
#pragma unroll
    for (int mt = 0; mt < 4; ++mt){
#pragma unroll
        for (int nt = 0; nt < 8; ++nt){
            int row = m0 + wm*64 + mt*16 + g;
            int col = n0 + wn*64 + nt*8 + 2*tig;
#pragma unroll
            for (int half = 0; half < 2; ++half){
                int r = row + half*8;
                float v0 = (acc[mt][nt][2*half+0] + bias[col])   * scale;
                float v1 = (acc[mt][nt][2*half+1] + bias[col+1]) * scale;
                if (mode == 0){
                    *(float2*)((float*)ga.dst + (size_t)r*DMODEL + col) = make_float2(v0, v1);
                } else {
                    int bb = r >> 11, s = r & 2047, h = col >> 6, d = col & 63;
                    *(__half2*)((__half*)ga.dst + (((size_t)(bb*NHEAD + h))*SEQ + s)*DK + d) =
                        __floats2half2_rn(v0, v1);
                }
            }
        }
    }
}

// ---------------- Flash attention fp16 + LDSM (proven R6 version) ----------------
#define CH   64
#define NCH  (SEQ/CH)   // 32
#define ASTRIDE 72      // halves per smem row
#define ATTN_SMEM_BYTES (2*2*(3*CH*ASTRIDE))   // K + V, 55,296 B

__global__ void __launch_bounds__(128,2) attn_kernel()
{
    extern __shared__ __half smh[];
    __half* sK = smh;                      // [3][64 keys][72]
    __half* sV = smh + 3*CH*ASTRIDE;       // [3][64 keys][72]

    const int tid  = threadIdx.x;
    const int warp = tid >> 5, lane = tid & 31;
    const int g = lane >> 2, tig = lane & 3;
    const int qt = blockIdx.x, bh = blockIdx.y;

    const __half* qg  = g_q + ((size_t)bh*SEQ + qt*128)*DK;  // pre-scaled by log2e/8
    const __half* kg0 = g_k + (size_t)bh*SEQ*DK;
    const __half* vg0 = g_v + (size_t)bh*SEQ*DK;

    auto load_kv = [&](int buf, int kt){
        const __half* kg = kg0 + (size_t)kt*CH*DK;
        const __half* vg = vg0 + (size_t)kt*CH*DK;
        __half* kb = sK + buf*(CH*ASTRIDE);
        __half* vb = sV + buf*(CH*ASTRIDE);
#pragma unroll
        for (int i = 0; i < 4; ++i){
            int v = i*128 + tid;
            int r = v >> 3, c = (v & 7) << 3;
            cp16(saddr(kb + r*ASTRIDE + c), kg + (size_t)r*DK + c);
            cp16(saddr(vb + r*ASTRIDE + c), vg + (size_t)r*DK + c);
        }
        cpcommit();
    };

    load_kv(0, 0);
    load_kv(1, 1);

    uint32_t qa[2][4][4];
    {
        const int r0 = warp*32 + g;
#pragma unroll
        for (int mt = 0; mt < 2; ++mt)
#pragma unroll
        for (int kk = 0; kk < 4; ++kk){
            int r = r0 + mt*16;
            int c = kk*16 + 2*tig;
            qa[mt][kk][0] = ldu32(qg + (size_t)r*DK + c);
            qa[mt][kk][1] = ldu32(qg + (size_t)(r+8)*DK + c);
            qa[mt][kk][2] = ldu32(qg + (size_t)r*DK + c + 8);
            qa[mt][kk][3] = ldu32(qg + (size_t)(r+8)*DK + c + 8);
        }
    }

    float o[2][8][4];
#pragma unroll
    for (int i=0;i<2;i++)
#pragma unroll
        for (int j=0;j<8;j++)
#pragma unroll
            for (int e=0;e<4;e++) o[i][j][e] = 0.f;
    float rm[2][2] = {{-1e30f,-1e30f},{-1e30f,-1e30f}};
    float rl[2][2] = {{0.f,0.f},{0.f,0.f}};

    const unsigned FULL = 0xffffffffu;
    const int lrow16 = lane & 15;
    const int lcol8  = (lane >> 4) << 3;
    const int brow   = (lane & 7) + lcol8;
    const int bcol8  = ((lane >> 3) & 1) << 3;
    const uint32_t sKa = saddr(sK), sVa = saddr(sV);

    for (int kt = 0; kt < NCH; ++kt){
        if (kt == NCH-1) cpwait<0>(); else cpwait<1>();
        __syncthreads();
        if (kt < NCH-2) load_kv((kt+2)%3, kt+2);

        const uint32_t kbuf = sKa + (kt%3)*(CH*ASTRIDE*2);
        const uint32_t vbuf = sVa + (kt%3)*(CH*ASTRIDE*2);

        float s[2][8][4];
#pragma unroll
        for (int i=0;i<2;i++)
#pragma unroll
            for (int j=0;j<8;j++)
#pragma unroll
                for (int e=0;e<4;e++) s[i][j][e] = 0.f;
#pragma unroll
        for (int kk = 0; kk < 4; ++kk){
#pragma unroll
            for (int ntp = 0; ntp < 4; ++ntp){
                uint32_t b0,b1,b2,b3;
                uint32_t a = kbuf + (((ntp*16 + brow)*ASTRIDE + kk*16 + bcol8) << 1);
                ldsm4(b0,b1,b2,b3, a);
                mma16(s[0][2*ntp  ], qa[0][kk][0],qa[0][kk][1],qa[0][kk][2],qa[0][kk][3], b0,b1);
                mma16(s[1][2*ntp  ], qa[1][kk][0],qa[1][kk][1],qa[1][kk][2],qa[1][kk][3], b0,b1);
                mma16(s[0][2*ntp+1], qa[0][kk][0],qa[0][kk][1],qa[0][kk][2],qa[0][kk][3], b2,b3);
                mma16(s[1][2*ntp+1], qa[1][kk][0],qa[1][kk][1],qa[1][kk][2],qa[1][kk][3], b2,b3);
            }
        }

#pragma unroll
        for (int mt = 0; mt < 2; ++mt){
            float m0 = -1e30f, m1 = -1e30f;
#pragma unroll
            for (int nt = 0; nt < 8; ++nt){
                m0 = fmaxf(m0, fmaxf(s[mt][nt][0], s[mt][nt][1]));
                m1 = fmaxf(m1, fmaxf(s[mt][nt][2], s[mt][nt][3]));
            }
            m0 = fmaxf(m0, __shfl_xor_sync(FULL, m0, 1));
            m0 = fmaxf(m0, __shfl_xor_sync(FULL, m0, 2));
            m1 = fmaxf(m1, __shfl_xor_sync(FULL, m1, 1));
            m1 = fmaxf(m1, __shfl_xor_sync(FULL, m1, 2));
            float nm0 = fmaxf(rm[mt][0], m0), nm1 = fmaxf(rm[mt][1], m1);
            bool upd = (nm0 != rm[mt][0]) || (nm1 != rm[mt][1]);

            float l0 = 0.f, l1 = 0.f;
#pragma unroll
            for (int nt = 0; nt < 8; ++nt){
                float p0 = exp2f(s[mt][nt][0] - nm0);
                float p1 = exp2f(s[mt][nt][1] - nm0);
                float p2 = exp2f(s[mt][nt][2] - nm1);
                float p3 = exp2f(s[mt][nt][3] - nm1);
                s[mt][nt][0] = p0; s[mt][nt][1] = p1;
                s[mt][nt][2] = p2; s[mt][nt][3] = p3;
                l0 += p0 + p1; l1 += p2 + p3;
            }
            l0 += __shfl_xor_sync(FULL, l0, 1);
            l0 += __shfl_xor_sync(FULL, l0, 2);
            l1 += __shfl_xor_sync(FULL, l1, 1);
            l1 += __shfl_xor_sync(FULL, l1, 2);

            if (__any_sync(FULL, upd)){
                float cor0 = exp2f(rm[mt][0] - nm0);
                float cor1 = exp2f(rm[mt][1] - nm1);
                rm[mt][0] = nm0; rm[mt][1] = nm1;
                rl[mt][0] = rl[mt][0]*cor0 + l0;
                rl[mt][1] = rl[mt][1]*cor1 + l1;
#pragma unroll
                for (int nt = 0; nt < 8; ++nt){
                    o[mt][nt][0] *= cor0; o[mt][nt][1] *= cor0;
                    o[mt][nt][2] *= cor1; o[mt][nt][3] *= cor1;
                }
            } else {
                rl[mt][0] += l0;
                rl[mt][1] += l1;
            }
        }

#pragma unroll
        for (int kk = 0; kk < 4; ++kk){
            uint32_t aP[2][4];
#pragma unroll
            for (int mt = 0; mt < 2; ++mt){
                aP[mt][0] = packh2(s[mt][2*kk  ][0], s[mt][2*kk  ][1]);
                aP[mt][1] = packh2(s[mt][2*kk  ][2], s[mt][2*kk  ][3]);
                aP[mt][2] = packh2(s[mt][2*kk+1][0], s[mt][2*kk+1][1]);
                aP[mt][3] = packh2(s[mt][2*kk+1][2], s[mt][2*kk+1][3]);
            }
#pragma unroll
            for (int dp = 0; dp < 4; ++dp){
                uint32_t b0,b1,b2,b3;
                uint32_t a = vbuf + (((kk*16 + lrow16)*ASTRIDE + dp*16 + lcol8) << 1);
                ldsm4t(b0,b1,b2,b3, a);
                mma16(o[0][2*dp  ], aP[0][0],aP[0][1],aP[0][2],aP[0][3], b0,b1);
                mma16(o[1][2*dp  ], aP[1][0],aP[1][1],aP[1][2],aP[1][3], b0,b1);
                mma16(o[0][2*dp+1], aP[0][0],aP[0][1],aP[0][2],aP[0][3], b2,b3);
                mma16(o[1][2*dp+1], aP[1][0],aP[1][1],aP[1][2],aP[1][3], b2,b3);
            }
        }
    }

    int b = bh >> 4, h = bh & 15;
#pragma unroll
    for (int mt = 0; mt < 2; ++mt){
        float il0 = 1.f/rl[mt][0], il1 = 1.f/rl[mt][1];
        int r0 = b*SEQ + qt*128 + warp*32 + mt*16 + g;
#pragma unroll
        for (int nt = 0; nt < 8; ++nt){
            int col = h*64 + nt*8 + 2*tig;
            *(__half2*)(g_ctx + (size_t)r0*DMODEL + col) =
                __floats2half2_rn(o[mt][nt][0]*il0, o[mt][nt][1]*il0);
            *(__half2*)(g_ctx + (size_t)(r0+8)*DMODEL + col) =
                __floats2half2_rn(o[mt][nt][2]*il1, o[mt][nt][3]*il1);
        }
    }
}

// ---------------- launch ----------------
extern "C" void kernel_launch(void* const* d_in, const int* in_sizes, int n_in,
                              void* d_out, int out_size)
{
    const float* Xq = (const float*)d_in[0];
    const float* Xk = (const float*)d_in[1];
    const float* Xv = (const float*)d_in[2];
    const float* Wq = (const float*)d_in[3]; const float* bq = (const float*)d_in[4];
    const float* Wk = (const float*)d_in[5]; const float* bk = (const float*)d_in[6];
    const float* Wv = (const float*)d_in[7]; const float* bv = (const float*)d_in[8];
    const float* Wo = (const float*)d_in[9]; const float* bo = (const float*)d_in[10];
    float* out = (float*)d_out;

    void *gq, *gk, *gv, *gctx, *gxq, *gxk, *gxv, *gwq, *gwk, *gwv, *gwo;
    cudaGetSymbolAddress(&gq,  g_q);
    cudaGetSymbolAddress(&gk,  g_k);
    cudaGetSymbolAddress(&gv,  g_v);
    cudaGetSymbolAddress(&gctx, g_ctx);
    cudaGetSymbolAddress(&gxq, g_xq);
    cudaGetSymbolAddress(&gxk, g_xk);
    cudaGetSymbolAddress(&gxv, g_xv);
    cudaGetSymbolAddress(&gwq, g_wq);
    cudaGetSymbolAddress(&gwk, g_wk);
    cudaGetSymbolAddress(&gwv, g_wv);
    cudaGetSymbolAddress(&gwo, g_wo);

    cudaFuncSetAttribute(gemm_fp16,  cudaFuncAttributeMaxDynamicSharedMemorySize, GEMM_SMEM_BYTES);
    cudaFuncSetAttribute(attn_kernel, cudaFuncAttributeMaxDynamicSharedMemorySize, ATTN_SMEM_BYTES);

    // convert raw inputs + weights to fp16 once
    {
        int n4x = (MROWS*DMODEL)/4;
        dim3 gx((n4x + 255)/256, 3);
        cvt3_kernel<<<gx, 256>>>((const float4*)Xq, (const float4*)Xk, (const float4*)Xv,
                                 (__half2*)gxq, (__half2*)gxk, (__half2*)gxv, n4x);
        int n4w = (DMODEL*DMODEL)/4;
        dim3 gw((n4w + 255)/256, 4);
        cvt4_kernel<<<gw, 256>>>((const float4*)Wq, (const float4*)Wk,
                                 (const float4*)Wv, (const float4*)Wo,
                                 (__half2*)gwq, (__half2*)gwk, (__half2*)gwv, (__half2*)gwo, n4w);
    }

    const float qscale = 0.125f * 1.4426950408889634f;   // 1/sqrt(dk) * log2(e)
    GemmArgs aq{(const __half*)gxq, (const __half*)gwq, bq, gq,   qscale, 1};
    GemmArgs ak{(const __half*)gxk, (const __half*)gwk, bk, gk,   1.0f,   1};
    GemmArgs av{(const __half*)gxv, (const __half*)gwv, bv, gv,   1.0f,   1};
    GemmArgs ao{(const __half*)gctx,(const __half*)gwo, bo, (void*)out, 1.0f, 0};

    // merged QKV: one launch, grid.z selects projection (1536 CTAs @ 2/SM)
    dim3 gqkv(DMODEL/128, MROWS/128, 3);
    gemm_fp16<<<gqkv, 128, GEMM_SMEM_BYTES>>>(aq, ak, av);

    attn_kernel<<<dim3(SEQ/128, BATCH*NHEAD), 128, ATTN_SMEM_BYTES>>>();

    dim3 go(DMODEL/128, MROWS/128, 1);
    gemm_fp16<<<go, 128, GEMM_SMEM_BYTES>>>(ao, ao, ao);
}

// round 9
// speedup vs baseline: 2.2175x; 1.0260x over previous
#include <cuda_runtime.h>
#include <cuda_fp16.h>
#include <cstdint>

#define SEQ    2048
#define BATCH  4
#define NHEAD  16
#define DK     64
#define DMODEL 1024
#define MROWS  (BATCH*SEQ)

// Scratch (allocation-free rule: device globals). All fp16.
__device__ __half g_q[BATCH*NHEAD*SEQ*DK];     // [b,h,s,d], pre-scaled by log2e/8
__device__ __half g_k[BATCH*NHEAD*SEQ*DK];     // [b,h,s,d]
__device__ __half g_v[BATCH*NHEAD*SEQ*DK];     // [b,h,s,d]
__device__ __half g_ctx[(size_t)MROWS*DMODEL]; // [b*s, d_model]
// fp16 copies of raw inputs / weights
__device__ __half g_xq[(size_t)MROWS*DMODEL];
__device__ __half g_xk[(size_t)MROWS*DMODEL];
__device__ __half g_xv[(size_t)MROWS*DMODEL];
__device__ __half g_wq[DMODEL*DMODEL];
__device__ __half g_wk[DMODEL*DMODEL];
__device__ __half g_wv[DMODEL*DMODEL];
__device__ __half g_wo[DMODEL*DMODEL];

// ---------------- helpers ----------------
__device__ __forceinline__ uint32_t saddr(const void* p){
    return (uint32_t)__cvta_generic_to_shared(p);
}
__device__ __forceinline__ void cp16(uint32_t s, const void* g){
    asm volatile("cp.async.cg.shared.global [%0], [%1], 16;\n" :: "r"(s), "l"(g));
}
__device__ __forceinline__ void cpcommit(){ asm volatile("cp.async.commit_group;\n"); }
template<int N> __device__ __forceinline__ void cpwait(){
    asm volatile("cp.async.wait_group %0;\n" :: "n"(N));
}
__device__ __forceinline__ void mma16(float c[4],
        uint32_t a0,uint32_t a1,uint32_t a2,uint32_t a3,
        uint32_t b0,uint32_t b1){
    asm volatile(
      "mma.sync.aligned.m16n8k16.row.col.f32.f16.f16.f32 "
      "{%0,%1,%2,%3},{%4,%5,%6,%7},{%8,%9},{%0,%1,%2,%3};\n"
      : "+f"(c[0]), "+f"(c[1]), "+f"(c[2]), "+f"(c[3])
      : "r"(a0), "r"(a1), "r"(a2), "r"(a3), "r"(b0), "r"(b1));
}
__device__ __forceinline__ void ldsm4(uint32_t& r0,uint32_t& r1,uint32_t& r2,uint32_t& r3,uint32_t a){
    asm volatile("ldmatrix.sync.aligned.m8n8.x4.shared.b16 {%0,%1,%2,%3}, [%4];"
      : "=r"(r0),"=r"(r1),"=r"(r2),"=r"(r3) : "r"(a));
}
__device__ __forceinline__ void ldsm4t(uint32_t& r0,uint32_t& r1,uint32_t& r2,uint32_t& r3,uint32_t a){
    asm volatile("ldmatrix.sync.aligned.m8n8.x4.trans.shared.b16 {%0,%1,%2,%3}, [%4];"
      : "=r"(r0),"=r"(r1),"=r"(r2),"=r"(r3) : "r"(a));
}
__device__ __forceinline__ uint32_t packh2(float lo, float hi){
    __half2 h = __floats2half2_rn(lo, hi);
    return *reinterpret_cast<uint32_t*>(&h);
}
__device__ __forceinline__ uint32_t ldu32(const __half* p){
    return *reinterpret_cast<const uint32_t*>(p);
}
// single-MUFU exponential (2-ulp; softmax renormalizes, error negligible)
__device__ __forceinline__ float ex2f(float x){
    float y; asm("ex2.approx.ftz.f32 %0, %1;" : "=f"(y) : "f"(x)); return y;
}

// ---------------- convert kernels (fp32 -> fp16 RN) ----------------
__global__ void cvt3_kernel(const float4* __restrict__ a, const float4* __restrict__ b,
                            const float4* __restrict__ c, __half2* __restrict__ oa,
                            __half2* __restrict__ ob, __half2* __restrict__ oc, int n4)
{
    int i = blockIdx.x*blockDim.x + threadIdx.x;
    if (i >= n4) return;
    const float4* s = (blockIdx.y==0) ? a : (blockIdx.y==1) ? b : c;
    __half2* d      = (blockIdx.y==0) ? oa : (blockIdx.y==1) ? ob : oc;
    float4 v = s[i];
    d[2*i]   = __floats2half2_rn(v.x, v.y);
    d[2*i+1] = __floats2half2_rn(v.z, v.w);
}
__global__ void cvt4_kernel(const float4* __restrict__ a, const float4* __restrict__ b,
                            const float4* __restrict__ c, const float4* __restrict__ e,
                            __half2* __restrict__ oa, __half2* __restrict__ ob,
                            __half2* __restrict__ oc, __half2* __restrict__ oe, int n4)
{
    int i = blockIdx.x*blockDim.x + threadIdx.x;
    if (i >= n4) return;
    const float4* s = (blockIdx.y==0) ? a : (blockIdx.y==1) ? b : (blockIdx.y==2) ? c : e;
    __half2* d      = (blockIdx.y==0) ? oa : (blockIdx.y==1) ? ob : (blockIdx.y==2) ? oc : oe;
    float4 v = s[i];
    d[2*i]   = __floats2half2_rn(v.x, v.y);
    d[2*i+1] = __floats2half2_rn(v.z, v.w);
}

// ---------------- GEMM fp16: C[M,N] = X[M,K] @ W[N,K]^T + bias ----------------
// 128-thread CTAs, block tile 128x128x64, 4 warps (2m x 2n), warp tile 64x64.
// 3-stage cp.async pipeline; LDSM fragments with 1-step B prefetch. 2 CTAs/SM.
// mode 0: dst fp32 [m,1024]; mode 1: dst fp16 [b,h,s,64], scaled.
struct GemmArgs { const __half* A; const __half* W; const float* bias;
                  void* dst; float scale; int mode; };

#define KT       64
#define GSTRIDE  72     // halves per smem row (64 + 8 pad) = 144B, LDSM conflict-free
#define GEMM_SMEM_BYTES (3*(128+128)*GSTRIDE*2)   // 110,592 B -> 2 CTAs/SM

__global__ void __launch_bounds__(128,2) gemm_fp16(GemmArgs ga0, GemmArgs ga1, GemmArgs ga2)
{
    extern __shared__ __half smh[];
    __half* sA = smh;                       // [3][128][72]
    __half* sB = smh + 3*128*GSTRIDE;       // [3][128][72]
    const int tid = threadIdx.x;
    const int m0 = blockIdx.y << 7, n0 = blockIdx.x << 7;

    GemmArgs ga = (blockIdx.z==0) ? ga0 : (blockIdx.z==1) ? ga1 : ga2;
    const __half* __restrict__ A = ga.A;
    const __half* __restrict__ W = ga.W;

    auto load_tile = [&](int buf, int kt){
        const __half* Ag = A + (size_t)m0*DMODEL + kt*KT;
        const __half* Wg = W + (size_t)n0*DMODEL + kt*KT;
        __half* a = sA + buf*(128*GSTRIDE);
        __half* b = sB + buf*(128*GSTRIDE);
#pragma unroll
        for (int i = 0; i < 8; ++i){
            int v = i*128 + tid;
            int r = v >> 3, c = (v & 7) << 3;
            cp16(saddr(a + r*GSTRIDE + c), Ag + (size_t)r*DMODEL + c);
            cp16(saddr(b + r*GSTRIDE + c), Wg + (size_t)r*DMODEL + c);
        }
        cpcommit();
    };

    float acc[4][8][4];
#pragma unroll
    for (int i=0;i<4;i++)
#pragma unroll
        for (int j=0;j<8;j++)
#pragma unroll
            for (int e=0;e<4;e++) acc[i][j][e] = 0.f;

    load_tile(0, 0);
    load_tile(1, 1);

    const int warp = tid >> 5, lane = tid & 31;
    const int wm = warp >> 1, wn = warp & 1;
    const int g = lane >> 2, tig = lane & 3;
    const int lrow16 = lane & 15;
    const int lcol8  = (lane >> 4) << 3;
    const int brow   = (lane & 7) + lcol8;
    const int bcol8  = ((lane >> 3) & 1) << 3;

    const uint32_t sAa = saddr(sA), sBa = saddr(sB);

    for (int kt = 0; kt < 16; ++kt){
        if (kt == 15) cpwait<0>(); else cpwait<1>();
        __syncthreads();
        if (kt < 14) load_tile((kt+2)%3, kt+2);

        const uint32_t abuf = sAa + (kt%3)*(128*GSTRIDE*2);
        const uint32_t bbuf = sBa + (kt%3)*(128*GSTRIDE*2);
#pragma unroll
        for (int ks = 0; ks < 4; ++ks){      // 4 x k16
            uint32_t af[4][4];
#pragma unroll
            for (int mt = 0; mt < 4; ++mt){
                uint32_t a = abuf + (((wm*64 + mt*16 + lrow16)*GSTRIDE + ks*16 + lcol8) << 1);
                ldsm4(af[mt][0], af[mt][1], af[mt][2], af[mt][3], a);
            }
            uint32_t bc[4], bn[4];
            ldsm4(bc[0],bc[1],bc[2],bc[3],
                  bbuf + (((wn*64 + brow)*GSTRIDE + ks*16 + bcol8) << 1));
#pragma unroll
            for (int ntp = 0; ntp < 4; ++ntp){
                if (ntp < 3)                 // prefetch next B frags
                    ldsm4(bn[0],bn[1],bn[2],bn[3],
                          bbuf + (((wn*64 + (ntp+1)*16 + brow)*GSTRIDE + ks*16 + bcol8) << 1));
#pragma unroll
                for (int mt = 0; mt < 4; ++mt){
                    mma16(acc[mt][2*ntp  ], af[mt][0],af[mt][1],af[mt][2],af[mt][3], bc[0],bc[1]);
                    mma16(acc[mt][2*ntp+1], af[mt][0],af[mt][1],af[mt][2],af[mt][3], bc[2],bc[3]);
                }
                if (ntp < 3){ bc[0]=bn[0]; bc[1]=bn[1]; bc[2]=bn[2]; bc[3]=bn[3]; }
            }
        }
    }

    // epilogue
    const float* bias = ga.bias;
    const float scale = ga.scale;
    const int mode = ga.mode;
#pragma unroll
    for (int mt = 0; mt < 4; ++mt){
#pragma unroll
        for (int nt = 0; nt < 8; ++nt){
            int row = m0 + wm*64 + mt*16 + g;
            int col = n0 + wn*64 + nt*8 + 2*tig;
#pragma unroll
            for (int half = 0; half < 2; ++half){
                int r = row + half*8;
                float v0 = (acc[mt][nt][2*half+0] + bias[col])   * scale;
                float v1 = (acc[mt][nt][2*half+1] + bias[col+1]) * scale;
                if (mode == 0){
                    *(float2*)((float*)ga.dst + (size_t)r*DMODEL + col) = make_float2(v0, v1);
                } else {
                    int bb = r >> 11, s = r & 2047, h = col >> 6, d = col & 63;
                    *(__half2*)((__half*)ga.dst + (((size_t)(bb*NHEAD + h))*SEQ + s)*DK + d) =
                        __floats2half2_rn(v0, v1);
                }
            }
        }
    }
}

// ---------------- Flash attention fp16 + LDSM + prefetch ----------------
#define CH   64
#define NCH  (SEQ/CH)   // 32
#define ASTRIDE 72      // halves per smem row
#define ATTN_SMEM_BYTES (2*2*(3*CH*ASTRIDE))   // K + V, 55,296 B

__global__ void __launch_bounds__(128,2) attn_kernel()
{
    extern __shared__ __half smh[];
    __half* sK = smh;                      // [3][64 keys][72]
    __half* sV = smh + 3*CH*ASTRIDE;       // [3][64 keys][72]

    const int tid  = threadIdx.x;
    const int warp = tid >> 5, lane = tid & 31;
    const int g = lane >> 2, tig = lane & 3;
    const int qt = blockIdx.x, bh = blockIdx.y;

    const __half* qg  = g_q + ((size_t)bh*SEQ + qt*128)*DK;  // pre-scaled by log2e/8
    const __half* kg0 = g_k + (size_t)bh*SEQ*DK;
    const __half* vg0 = g_v + (size_t)bh*SEQ*DK;

    auto load_kv = [&](int buf, int kt){
        const __half* kg = kg0 + (size_t)kt*CH*DK;
        const __half* vg = vg0 + (size_t)kt*CH*DK;
        __half* kb = sK + buf*(CH*ASTRIDE);
        __half* vb = sV + buf*(CH*ASTRIDE);
#pragma unroll
        for (int i = 0; i < 4; ++i){
            int v = i*128 + tid;
            int r = v >> 3, c = (v & 7) << 3;
            cp16(saddr(kb + r*ASTRIDE + c), kg + (size_t)r*DK + c);
            cp16(saddr(vb + r*ASTRIDE + c), vg + (size_t)r*DK + c);
        }
        cpcommit();
    };

    load_kv(0, 0);
    load_kv(1, 1);

    uint32_t qa[2][4][4];
    {
        const int r0 = warp*32 + g;
#pragma unroll
        for (int mt = 0; mt < 2; ++mt)
#pragma unroll
        for (int kk = 0; kk < 4; ++kk){
            int r = r0 + mt*16;
            int c = kk*16 + 2*tig;
            qa[mt][kk][0] = ldu32(qg + (size_t)r*DK + c);
            qa[mt][kk][1] = ldu32(qg + (size_t)(r+8)*DK + c);
            qa[mt][kk][2] = ldu32(qg + (size_t)r*DK + c + 8);
            qa[mt][kk][3] = ldu32(qg + (size_t)(r+8)*DK + c + 8);
        }
    }

    float o[2][8][4];
#pragma unroll
    for (int i=0;i<2;i++)
#pragma unroll
        for (int j=0;j<8;j++)
#pragma unroll
            for (int e=0;e<4;e++) o[i][j][e] = 0.f;
    float rm[2][2] = {{-1e30f,-1e30f},{-1e30f,-1e30f}};
    float rl[2][2] = {{0.f,0.f},{0.f,0.f}};

    const unsigned FULL = 0xffffffffu;
    const int lrow16 = lane & 15;
    const int lcol8  = (lane >> 4) << 3;
    const int brow   = (lane & 7) + lcol8;
    const int bcol8  = ((lane >> 3) & 1) << 3;
    const uint32_t sKa = saddr(sK), sVa = saddr(sV);

    for (int kt = 0; kt < NCH; ++kt){
        if (kt == NCH-1) cpwait<0>(); else cpwait<1>();
        __syncthreads();
        if (kt < NCH-2) load_kv((kt+2)%3, kt+2);

        const uint32_t kbuf = sKa + (kt%3)*(CH*ASTRIDE*2);
        const uint32_t vbuf = sVa + (kt%3)*(CH*ASTRIDE*2);

        // S[32 x 64] = q @ K^T with 1-step K-fragment prefetch
        float s[2][8][4];
#pragma unroll
        for (int i=0;i<2;i++)
#pragma unroll
            for (int j=0;j<8;j++)
#pragma unroll
                for (int e=0;e<4;e++) s[i][j][e] = 0.f;
        {
            uint32_t bc[4], bn[4];
            ldsm4(bc[0],bc[1],bc[2],bc[3], kbuf + (((brow)*ASTRIDE + bcol8) << 1));
#pragma unroll
            for (int kk = 0; kk < 4; ++kk){
#pragma unroll
                for (int ntp = 0; ntp < 4; ++ntp){
                    const bool has = !(kk==3 && ntp==3);
                    if (has){
                        const int nkk = (ntp==3) ? kk+1 : kk;
                        const int nntp = (ntp==3) ? 0 : ntp+1;
                        ldsm4(bn[0],bn[1],bn[2],bn[3],
                              kbuf + (((nntp*16 + brow)*ASTRIDE + nkk*16 + bcol8) << 1));
                    }
                    mma16(s[0][2*ntp  ], qa[0][kk][0],qa[0][kk][1],qa[0][kk][2],qa[0][kk][3], bc[0],bc[1]);
                    mma16(s[1][2*ntp  ], qa[1][kk][0],qa[1][kk][1],qa[1][kk][2],qa[1][kk][3], bc[0],bc[1]);
                    mma16(s[0][2*ntp+1], qa[0][kk][0],qa[0][kk][1],qa[0][kk][2],qa[0][kk][3], bc[2],bc[3]);
                    mma16(s[1][2*ntp+1], qa[1][kk][0],qa[1][kk][1],qa[1][kk][2],qa[1][kk][3], bc[2],bc[3]);
                    if (has){ bc[0]=bn[0]; bc[1]=bn[1]; bc[2]=bn[2]; bc[3]=bn[3]; }
                }
            }
        }

        // online softmax in log2 domain (rows private to warp)
#pragma unroll
        for (int mt = 0; mt < 2; ++mt){
            float m0 = -1e30f, m1 = -1e30f;
#pragma unroll
            for (int nt = 0; nt < 8; ++nt){
                m0 = fmaxf(m0, fmaxf(s[mt][nt][0], s[mt][nt][1]));
                m1 = fmaxf(m1, fmaxf(s[mt][nt][2], s[mt][nt][3]));
            }
            m0 = fmaxf(m0, __shfl_xor_sync(FULL, m0, 1));
            m0 = fmaxf(m0, __shfl_xor_sync(FULL, m0, 2));
            m1 = fmaxf(m1, __shfl_xor_sync(FULL, m1, 1));
            m1 = fmaxf(m1, __shfl_xor_sync(FULL, m1, 2));
            float nm0 = fmaxf(rm[mt][0], m0), nm1 = fmaxf(rm[mt][1], m1);
            bool upd = (nm0 != rm[mt][0]) || (nm1 != rm[mt][1]);

            float l0 = 0.f, l1 = 0.f;
#pragma unroll
            for (int nt = 0; nt < 8; ++nt){
                float p0 = ex2f(s[mt][nt][0] - nm0);
                float p1 = ex2f(s[mt][nt][1] - nm0);
                float p2 = ex2f(s[mt][nt][2] - nm1);
                float p3 = ex2f(s[mt][nt][3] - nm1);
                s[mt][nt][0] = p0; s[mt][nt][1] = p1;
                s[mt][nt][2] = p2; s[mt][nt][3] = p3;
                l0 += p0 + p1; l1 += p2 + p3;
            }
            l0 += __shfl_xor_sync(FULL, l0, 1);
            l0 += __shfl_xor_sync(FULL, l0, 2);
            l1 += __shfl_xor_sync(FULL, l1, 1);
            l1 += __shfl_xor_sync(FULL, l1, 2);

            if (__any_sync(FULL, upd)){       // warp-uniform; exact (ex2(0)==1)
                float cor0 = ex2f(rm[mt][0] - nm0);
                float cor1 = ex2f(rm[mt][1] - nm1);
                rm[mt][0] = nm0; rm[mt][1] = nm1;
                rl[mt][0] = rl[mt][0]*cor0 + l0;
                rl[mt][1] = rl[mt][1]*cor1 + l1;
#pragma unroll
                for (int nt = 0; nt < 8; ++nt){
                    o[mt][nt][0] *= cor0; o[mt][nt][1] *= cor0;
                    o[mt][nt][2] *= cor1; o[mt][nt][3] *= cor1;
                }
            } else {
                rl[mt][0] += l0;
                rl[mt][1] += l1;
            }
        }

        // O += P @ V with 1-step V-fragment prefetch
        {
            uint32_t vc[4], vn[4];
            ldsm4t(vc[0],vc[1],vc[2],vc[3], vbuf + (((lrow16)*ASTRIDE + lcol8) << 1));
#pragma unroll
            for (int kk = 0; kk < 4; ++kk){
                uint32_t aP[2][4];
#pragma unroll
                for (int mt = 0; mt < 2; ++mt){
                    aP[mt][0] = packh2(s[mt][2*kk  ][0], s[mt][2*kk  ][1]);
                    aP[mt][1] = packh2(s[mt][2*kk  ][2], s[mt][2*kk  ][3]);
                    aP[mt][2] = packh2(s[mt][2*kk+1][0], s[mt][2*kk+1][1]);
                    aP[mt][3] = packh2(s[mt][2*kk+1][2], s[mt][2*kk+1][3]);
                }
#pragma unroll
                for (int dp = 0; dp < 4; ++dp){
                    const bool has = !(kk==3 && dp==3);
                    if (has){
                        const int nkk = (dp==3) ? kk+1 : kk;
                        const int ndp = (dp==3) ? 0 : dp+1;
                        ldsm4t(vn[0],vn[1],vn[2],vn[3],
                               vbuf + (((nkk*16 + lrow16)*ASTRIDE + ndp*16 + lcol8) << 1));
                    }
                    mma16(o[0][2*dp  ], aP[0][0],aP[0][1],aP[0][2],aP[0][3], vc[0],vc[1]);
                    mma16(o[1][2*dp  ], aP[1][0],aP[1][1],aP[1][2],aP[1][3], vc[0],vc[1]);
                    mma16(o[0][2*dp+1], aP[0][0],aP[0][1],aP[0][2],aP[0][3], vc[2],vc[3]);
                    mma16(o[1][2*dp+1], aP[1][0],aP[1][1],aP[1][2],aP[1][3], vc[2],vc[3]);
                    if (has){ vc[0]=vn[0]; vc[1]=vn[1]; vc[2]=vn[2]; vc[3]=vn[3]; }
                }
            }
        }
    }

    int b = bh >> 4, h = bh & 15;
#pragma unroll
    for (int mt = 0; mt < 2; ++mt){
        float il0 = 1.f/rl[mt][0], il1 = 1.f/rl[mt][1];
        int r0 = b*SEQ + qt*128 + warp*32 + mt*16 + g;
#pragma unroll
        for (int nt = 0; nt < 8; ++nt){
            int col = h*64 + nt*8 + 2*tig;
            *(__half2*)(g_ctx + (size_t)r0*DMODEL + col) =
                __floats2half2_rn(o[mt][nt][0]*il0, o[mt][nt][1]*il0);
            *(__half2*)(g_ctx + (size_t)(r0+8)*DMODEL + col) =
                __floats2half2_rn(o[mt][nt][2]*il1, o[mt][nt][3]*il1);
        }
    }
}

// ---------------- launch ----------------
extern "C" void kernel_launch(void* const* d_in, const int* in_sizes, int n_in,
                              void* d_out, int out_size)
{
    const float* Xq = (const float*)d_in[0];
    const float* Xk = (const float*)d_in[1];
    const float* Xv = (const float*)d_in[2];
    const float* Wq = (const float*)d_in[3]; const float* bq = (const float*)d_in[4];
    const float* Wk = (const float*)d_in[5]; const float* bk = (const float*)d_in[6];
    const float* Wv = (const float*)d_in[7]; const float* bv = (const float*)d_in[8];
    const float* Wo = (const float*)d_in[9]; const float* bo = (const float*)d_in[10];
    float* out = (float*)d_out;

    void *gq, *gk, *gv, *gctx, *gxq, *gxk, *gxv, *gwq, *gwk, *gwv, *gwo;
    cudaGetSymbolAddress(&gq,  g_q);
    cudaGetSymbolAddress(&gk,  g_k);
    cudaGetSymbolAddress(&gv,  g_v);
    cudaGetSymbolAddress(&gctx, g_ctx);
    cudaGetSymbolAddress(&gxq, g_xq);
    cudaGetSymbolAddress(&gxk, g_xk);
    cudaGetSymbolAddress(&gxv, g_xv);
    cudaGetSymbolAddress(&gwq, g_wq);
    cudaGetSymbolAddress(&gwk, g_wk);
    cudaGetSymbolAddress(&gwv, g_wv);
    cudaGetSymbolAddress(&gwo, g_wo);

    cudaFuncSetAttribute(gemm_fp16,  cudaFuncAttributeMaxDynamicSharedMemorySize, GEMM_SMEM_BYTES);
    cudaFuncSetAttribute(attn_kernel, cudaFuncAttributeMaxDynamicSharedMemorySize, ATTN_SMEM_BYTES);

    // convert raw inputs + weights to fp16 once
    {
        int n4x = (MROWS*DMODEL)/4;
        dim3 gx((n4x + 255)/256, 3);
        cvt3_kernel<<<gx, 256>>>((const float4*)Xq, (const float4*)Xk, (const float4*)Xv,
                                 (__half2*)gxq, (__half2*)gxk, (__half2*)gxv, n4x);
        int n4w = (DMODEL*DMODEL)/4;
        dim3 gw((n4w + 255)/256, 4);
        cvt4_kernel<<<gw, 256>>>((const float4*)Wq, (const float4*)Wk,
                                 (const float4*)Wv, (const float4*)Wo,
                                 (__half2*)gwq, (__half2*)gwk, (__half2*)gwv, (__half2*)gwo, n4w);
    }

    const float qscale = 0.125f * 1.4426950408889634f;   // 1/sqrt(dk) * log2(e)
    GemmArgs aq{(const __half*)gxq, (const __half*)gwq, bq, gq,   qscale, 1};
    GemmArgs ak{(const __half*)gxk, (const __half*)gwk, bk, gk,   1.0f,   1};
    GemmArgs av{(const __half*)gxv, (const __half*)gwv, bv, gv,   1.0f,   1};
    GemmArgs ao{(const __half*)gctx,(const __half*)gwo, bo, (void*)out, 1.0f, 0};

    // merged QKV: one launch, grid.z selects projection (1536 CTAs @ 2/SM)
    dim3 gqkv(DMODEL/128, MROWS/128, 3);
    gemm_fp16<<<gqkv, 128, GEMM_SMEM_BYTES>>>(aq, ak, av);

    attn_kernel<<<dim3(SEQ/128, BATCH*NHEAD), 128, ATTN_SMEM_BYTES>>>();

    dim3 go(DMODEL/128, MROWS/128, 1);
    gemm_fp16<<<go, 128, GEMM_SMEM_BYTES>>>(ao, ao, ao);
}